// round 14
// baseline (speedup 1.0000x reference)
#include <cuda_runtime.h>
#include <cuda_bf16.h>
#include <math.h>

#define Nn 2
#define Cc 32
#define NCk 4
#define Pp 884736            // 96*96*96
#define Pp4 221184           // Pp/4
#define NNCP 7077888         // Nn*NCk*Pp
#define NNCP4 1769472        // NNCP/4
#define U4v 884736           // NNCP/8 (uint4 bf16x8 units)
#define NCP  56623104        // Nn*Cc*Pp
#define SLICE 2304           // 96*24 float4 units per (nk,d) slice

#define PINF  __int_as_float(0x7f800000)
#define NINF  __int_as_float(0xff800000)
#define BNEG2 0xFF80FF80u    // bf16x2 {-inf,-inf}

typedef unsigned long long u64;
typedef unsigned int u32;

// ---------------- f32x2 helpers ----------------
__device__ __forceinline__ u64 pack2(float lo, float hi) {
    u64 r; asm("mov.b64 %0,{%1,%2};" : "=l"(r) : "f"(lo), "f"(hi)); return r;
}
__device__ __forceinline__ void unpack2(u64 v, float& lo, float& hi) {
    asm("mov.b64 {%0,%1},%2;" : "=f"(lo), "=f"(hi) : "l"(v));
}
__device__ __forceinline__ u64 ffma2(u64 a, u64 b, u64 c) {
    u64 d; asm("fma.rn.f32x2 %0,%1,%2,%3;" : "=l"(d) : "l"(a), "l"(b), "l"(c)); return d;
}
__device__ __forceinline__ u64 fmul2(u64 a, u64 b) {
    u64 d; asm("mul.rn.f32x2 %0,%1,%2;" : "=l"(d) : "l"(a), "l"(b)); return d;
}
__device__ __forceinline__ void ldg2x2(const float* p, u64& a, u64& b) {
    asm volatile("ld.global.v2.u64 {%0,%1},[%2];" : "=l"(a), "=l"(b) : "l"(p));
}
__device__ __forceinline__ void stg2x2(float* p, u64 a, u64 b) {
    asm volatile("st.global.v2.u64 [%0],{%1,%2};" :: "l"(p), "l"(a), "l"(b) : "memory");
}
__device__ __forceinline__ u32 packbf2(float lo, float hi) {
    u32 r; asm("cvt.rn.bf16x2.f32 %0,%1,%2;" : "=r"(r) : "f"(hi), "f"(lo)); return r;
}
__device__ __forceinline__ void bf4_to_f32x2(uint2 v, u64& A, u64& B) {
    A = pack2(__uint_as_float(v.x << 16), __uint_as_float(v.x & 0xFFFF0000u));
    B = pack2(__uint_as_float(v.y << 16), __uint_as_float(v.y & 0xFFFF0000u));
}
__device__ __forceinline__ u32 bmax2(u32 a, u32 b) {
    __nv_bfloat162 r = __hmax2(*reinterpret_cast<__nv_bfloat162*>(&a),
                               *reinterpret_cast<__nv_bfloat162*>(&b));
    return *reinterpret_cast<u32*>(&r);
}
__device__ __forceinline__ uint4 bmax8(uint4 a, uint4 b) {
    return make_uint4(bmax2(a.x,b.x), bmax2(a.y,b.y), bmax2(a.z,b.z), bmax2(a.w,b.w));
}
__device__ __forceinline__ float sigf(float v) { return 1.0f / (1.0f + __expf(-v)); }

// ---------------- scratch ----------------
__device__ __align__(16) __nv_bfloat16 g_A[NNCP];    // dilation final
__device__ __align__(16) __nv_bfloat16 g_B[NNCP];    // hw-pooled
__device__ __align__(16) __nv_bfloat16 g_ero[NNCP];

__device__ float  g_parte[768];    // one per (nk,d) slice
__device__ float  g_partd[1728];
__device__ double g_sum_fe[Nn * NCk * Cc];
__device__ double g_sum_fd[Nn * NCk * Cc];
__device__ double g_sum_f [Nn * Cc];
__device__ double g_ch_sq [Cc];
__device__ double g_W0    [Nn * NCk];
__device__ float  g_dclu[Nn * NCk * Cc];
__device__ float  g_base[Nn * Cc];
__device__ float  g_scale[Cc];
__device__ float  g_shift[Cc];

__device__ __forceinline__ float4 vmin4(float4 a, float4 b) {
    return make_float4(fminf(a.x,b.x), fminf(a.y,b.y), fminf(a.z,b.z), fminf(a.w,b.w));
}
__device__ __forceinline__ float4 vmax4f(float4 a, float4 b) {
    return make_float4(fmaxf(a.x,b.x), fmaxf(a.y,b.y), fmaxf(a.z,b.z), fmaxf(a.w,b.w));
}

// ---------------- fused: h-pool + w-pool (smem slice) + full erode + partial ero sums + zeroing ----------------
// grid (96 d, 8 nk) x 256 threads; each thread 9 f4 units of the 2304-unit slice.
__global__ void __launch_bounds__(256) k_pool_hw_erode(const float4* __restrict__ x4) {
    __shared__ float4 s_h[SLICE];
    __shared__ float s_red[8];
    int t = threadIdx.x;
    int d = blockIdx.x;
    int nk = blockIdx.y;
    if (d == 0 && nk == 0) {
        if (t < 256) { g_sum_fe[t] = 0.0; g_sum_fd[t] = 0.0; }
        if (t < 64)  g_sum_f[t] = 0.0;
        if (t < 32)  g_ch_sq[t] = 0.0;
        if (t < 8)   g_W0[t] = 0.0;
    }
    size_t base = (size_t)(nk * 96 + d) * SLICE;
    float esum = 0.f;

#pragma unroll
    for (int j = 0; j < 9; j++) {
        int i = t + j * 256;
        int h4 = i % 24;
        int w = i / 24;
        size_t gi = base + i;
        bool hasP = (h4 >= 1), hasN = (h4 <= 22);
        float4 cur = x4[gi];
        float4 pv = make_float4(0,0,0,0), nv = make_float4(0,0,0,0);
        if (hasP) pv = x4[gi - 1];
        if (hasN) nv = x4[gi + 1];
        // h-max (NINF pad) -> smem
        {
            float s[12];
            s[0] = hasP ? pv.x : NINF; s[1] = hasP ? pv.y : NINF;
            s[2] = hasP ? pv.z : NINF; s[3] = hasP ? pv.w : NINF;
            s[4]=cur.x; s[5]=cur.y; s[6]=cur.z; s[7]=cur.w;
            s[8] = hasN ? nv.x : NINF; s[9] = hasN ? nv.y : NINF;
            s[10]= hasN ? nv.z : NINF; s[11]= hasN ? nv.w : NINF;
            float4 o;
            o.x = fmaxf(fmaxf(fmaxf(s[2],s[3]), fmaxf(s[4],s[5])), s[6]);
            o.y = fmaxf(fmaxf(fmaxf(s[3],s[4]), fmaxf(s[5],s[6])), s[7]);
            o.z = fmaxf(fmaxf(fmaxf(s[4],s[5]), fmaxf(s[6],s[7])), s[8]);
            o.w = fmaxf(fmaxf(fmaxf(s[5],s[6]), fmaxf(s[7],s[8])), s[9]);
            s_h[i] = o;
        }
        // erode (PINF pad) + sigmoid -> g_ero bf16
        {
            float s[12];
            s[0] = hasP ? pv.x : PINF; s[1] = hasP ? pv.y : PINF;
            s[2] = hasP ? pv.z : PINF; s[3] = hasP ? pv.w : PINF;
            s[4]=cur.x; s[5]=cur.y; s[6]=cur.z; s[7]=cur.w;
            s[8] = hasN ? nv.x : PINF; s[9] = hasN ? nv.y : PINF;
            s[10]= hasN ? nv.z : PINF; s[11]= hasN ? nv.w : PINF;
            float4 m;
            m.x = fminf(fminf(fminf(s[2],s[3]), fminf(s[4],s[5])), s[6]);
            m.y = fminf(fminf(fminf(s[3],s[4]), fminf(s[5],s[6])), s[7]);
            m.z = fminf(fminf(fminf(s[4],s[5]), fminf(s[6],s[7])), s[8]);
            m.w = fminf(fminf(fminf(s[5],s[6]), fminf(s[7],s[8])), s[9]);
            if (w >= 1)  m = vmin4(m, x4[gi - 24]);
            if (w >= 2)  m = vmin4(m, x4[gi - 48]);
            if (w <= 94) m = vmin4(m, x4[gi + 24]);
            if (w <= 93) m = vmin4(m, x4[gi + 48]);
            if (d >= 1)  m = vmin4(m, x4[gi - 2304]);
            if (d >= 2)  m = vmin4(m, x4[gi - 4608]);
            if (d <= 94) m = vmin4(m, x4[gi + 2304]);
            if (d <= 93) m = vmin4(m, x4[gi + 4608]);
            m.x = sigf(m.x); m.y = sigf(m.y); m.z = sigf(m.z); m.w = sigf(m.w);
            reinterpret_cast<uint2*>(g_ero)[gi] = make_uint2(packbf2(m.x,m.y), packbf2(m.z,m.w));
            esum += (m.x + m.y) + (m.z + m.w);
        }
    }
    __syncthreads();
    // w-pool from smem -> g_B bf16
#pragma unroll
    for (int j = 0; j < 9; j++) {
        int i = t + j * 256;
        int w = i / 24;
        float4 m = s_h[i];
        if (w >= 1)  m = vmax4f(m, s_h[i - 24]);
        if (w >= 2)  m = vmax4f(m, s_h[i - 48]);
        if (w <= 94) m = vmax4f(m, s_h[i + 24]);
        if (w <= 93) m = vmax4f(m, s_h[i + 48]);
        reinterpret_cast<uint2*>(g_B)[base + i] = make_uint2(packbf2(m.x,m.y), packbf2(m.z,m.w));
    }
    // partial ero sum (one slice per block)
#pragma unroll
    for (int o = 16; o; o >>= 1) esum += __shfl_down_sync(0xffffffffu, esum, o);
    if ((t & 31) == 0) s_red[t >> 5] = esum;
    __syncthreads();
    if (t == 0) {
        float bsum = 0.f;
#pragma unroll
        for (int wv = 0; wv < 8; wv++) bsum += s_red[wv];
        g_parte[nk * 96 + d] = bsum;
    }
}

// ---------------- pool along D (bf16), paired + sigmoid + partial dil sums, g_B -> g_A ----------------
__device__ __forceinline__ u32 sig_bf2(u32 bits, float& acc) {
    float f0 = sigf(__uint_as_float(bits << 16));
    float f1 = sigf(__uint_as_float(bits & 0xFFFF0000u));
    acc += f0 + f1;
    return packbf2(f0, f1);
}
__global__ void __launch_bounds__(256) k_pool_d() {
    int j = blockIdx.x * blockDim.x + threadIdx.x;
    int t = threadIdx.x;
    __shared__ float s_red[8];
    const uint4* __restrict__ in = reinterpret_cast<const uint4*>(g_B);
    uint4* __restrict__ outp = reinterpret_cast<uint4*>(g_A);
    int hh = j % 1152;
    int dp = (j / 1152) % 48;
    int nk = j / 55296;
    int i0 = nk * 110592 + dp * 2304 + hh;
    const uint4 NEG = make_uint4(BNEG2, BNEG2, BNEG2, BNEG2);
    uint4 c0 = in[i0];
    uint4 p1 = in[i0 + 1152];
    uint4 m1 = (dp >= 1) ? in[i0 - 1152] : NEG;
    uint4 m2 = (dp >= 1) ? in[i0 - 2304] : NEG;
    uint4 p2 = (dp <= 46) ? in[i0 + 2304] : NEG;
    uint4 p3 = (dp <= 46) ? in[i0 + 3456] : NEG;
    uint4 o0 = bmax8(bmax8(bmax8(m2, m1), bmax8(c0, p1)), p2);
    uint4 o1 = bmax8(bmax8(bmax8(m1, c0), bmax8(p1, p2)), p3);
    float dsum = 0.f;
    o0.x = sig_bf2(o0.x, dsum); o0.y = sig_bf2(o0.y, dsum);
    o0.z = sig_bf2(o0.z, dsum); o0.w = sig_bf2(o0.w, dsum);
    o1.x = sig_bf2(o1.x, dsum); o1.y = sig_bf2(o1.y, dsum);
    o1.z = sig_bf2(o1.z, dsum); o1.w = sig_bf2(o1.w, dsum);
    outp[i0] = o0;
    outp[i0 + 1152] = o1;
#pragma unroll
    for (int o = 16; o; o >>= 1) dsum += __shfl_down_sync(0xffffffffu, dsum, o);
    if ((t & 31) == 0) s_red[t >> 5] = dsum;
    __syncthreads();
    if (t == 0) {
        float bsum = 0.f;
#pragma unroll
        for (int wv = 0; wv < 8; wv++) bsum += s_red[wv];
        g_partd[blockIdx.x] = bsum;
    }
}

// ---------------- contraction (bf16 masks, register double-buffered) ----------------
#define K4_ITER 32
__device__ __forceinline__ void k4_loadED(const __nv_bfloat16* __restrict__ eb,
                                          const __nv_bfloat16* __restrict__ db,
                                          size_t p, uint2 ev[4], uint2 dv[4]) {
#pragma unroll
    for (int k = 0; k < 4; k++) {
        ev[k] = *reinterpret_cast<const uint2*>(eb + (size_t)k * Pp + p);
        dv[k] = *reinterpret_cast<const uint2*>(db + (size_t)k * Pp + p);
    }
}
__device__ __forceinline__ void k4_body(const float* __restrict__ fb, int c0, size_t p,
                                        const uint2 ev[4], const uint2 dv[4],
                                        u64 acc_e[2][4], u64 acc_d[2][4], u64 accf[2], u64 one2) {
    u64 fA0, fB0, fA1, fB1;
    ldg2x2(fb + (size_t)c0 * Pp + p, fA0, fB0);
    ldg2x2(fb + (size_t)(c0 + 1) * Pp + p, fA1, fB1);
    u64 eA[4], eB[4], dA[4], dB[4];
#pragma unroll
    for (int k = 0; k < 4; k++) {
        bf4_to_f32x2(ev[k], eA[k], eB[k]);
        bf4_to_f32x2(dv[k], dA[k], dB[k]);
    }
    accf[0] = ffma2(fA0, one2, accf[0]); accf[0] = ffma2(fB0, one2, accf[0]);
    accf[1] = ffma2(fA1, one2, accf[1]); accf[1] = ffma2(fB1, one2, accf[1]);
#pragma unroll
    for (int k = 0; k < 4; k++) {
        acc_e[0][k] = ffma2(fA0, eA[k], acc_e[0][k]);
        acc_e[0][k] = ffma2(fB0, eB[k], acc_e[0][k]);
        acc_d[0][k] = ffma2(fA0, dA[k], acc_d[0][k]);
        acc_d[0][k] = ffma2(fB0, dB[k], acc_d[0][k]);
        acc_e[1][k] = ffma2(fA1, eA[k], acc_e[1][k]);
        acc_e[1][k] = ffma2(fB1, eB[k], acc_e[1][k]);
        acc_d[1][k] = ffma2(fA1, dA[k], acc_d[1][k]);
        acc_d[1][k] = ffma2(fB1, dB[k], acc_d[1][k]);
    }
}
__global__ void __launch_bounds__(512, 1) k4_contract(const float* __restrict__ feat) {
    int n = blockIdx.y;
    int warp = threadIdx.x >> 5;
    int lane = threadIdx.x & 31;
    int c0 = warp * 2;
    int q0 = blockIdx.x * (32 * K4_ITER) + lane;

    const float* __restrict__ fb = feat + (size_t)n * Cc * Pp;
    const __nv_bfloat16* __restrict__ eb = g_ero + (size_t)n * NCk * Pp;
    const __nv_bfloat16* __restrict__ db = g_A   + (size_t)n * NCk * Pp;

    u64 acc_e[2][4], acc_d[2][4], accf[2];
#pragma unroll
    for (int j = 0; j < 2; j++) {
        accf[j] = 0ull;
#pragma unroll
        for (int k = 0; k < 4; k++) { acc_e[j][k] = 0ull; acc_d[j][k] = 0ull; }
    }
    const u64 one2 = pack2(1.0f, 1.0f);

    uint2 e0[4], d0[4], e1[4], d1[4];
    size_t p = (size_t)q0 * 4;
    k4_loadED(eb, db, p, e0, d0);
    for (int i = 0; i < K4_ITER; i += 2) {
        size_t pn = p + 128;
        k4_loadED(eb, db, pn, e1, d1);
        k4_body(fb, c0, p, e0, d0, acc_e, acc_d, accf, one2);
        size_t pn2 = p + 256;
        if (i + 2 < K4_ITER) k4_loadED(eb, db, pn2, e0, d0);
        k4_body(fb, c0, pn, e1, d1, acc_e, acc_d, accf, one2);
        p = pn2;
    }

#pragma unroll
    for (int j = 0; j < 2; j++) {
#pragma unroll
        for (int k = 0; k < 4; k++) {
            float l0, h0, l1, h1;
            unpack2(acc_e[j][k], l0, h0);
            unpack2(acc_d[j][k], l1, h1);
            float ae = l0 + h0, ad = l1 + h1;
#pragma unroll
            for (int o = 16; o; o >>= 1) {
                ae += __shfl_down_sync(0xffffffffu, ae, o);
                ad += __shfl_down_sync(0xffffffffu, ad, o);
            }
            if (lane == 0) {
                atomicAdd(&g_sum_fe[(n * NCk + k) * Cc + c0 + j], (double)ae);
                atomicAdd(&g_sum_fd[(n * NCk + k) * Cc + c0 + j], (double)ad);
            }
        }
        float lf, hf;
        unpack2(accf[j], lf, hf);
        float af = lf + hf;
#pragma unroll
        for (int o = 16; o; o >>= 1) af += __shfl_down_sync(0xffffffffu, af, o);
        if (lane == 0) atomicAdd(&g_sum_f[n * Cc + c0 + j], (double)af);
    }
}

// ---------------- cluster build + partial reduction ----------------
__global__ void k5_cluster() {
    __shared__ float s_back[Nn][NCk][Cc];
    __shared__ double s_se[8], s_sd[8];
    int t = threadIdx.x;
    int warp = t >> 5, lane = t & 31;
    {
        double se = 0.0;
        for (int j = lane; j < 96; j += 32) se += (double)g_parte[warp * 96 + j];
        double sd = 0.0;
        for (int j = lane; j < 216; j += 32) sd += (double)g_partd[warp * 216 + j];
#pragma unroll
        for (int o = 16; o; o >>= 1) {
            se += __shfl_down_sync(0xffffffffu, se, o);
            sd += __shfl_down_sync(0xffffffffu, sd, o);
        }
        if (lane == 0) { s_se[warp] = se; s_sd[warp] = sd; }
    }
    __syncthreads();
    int n = t >> 7;
    int k = (t >> 5) & 3;
    int c = t & 31;
    double es = s_se[n * NCk + k] + 1e-5;
    double ds = s_sd[n * NCk + k] + 1e-5;
    double bs = (double)Pp - s_sd[n * NCk + k] + 1e-5;
    double fe = g_sum_fe[(n * NCk + k) * Cc + c];
    double fd = g_sum_fd[(n * NCk + k) * Cc + c];
    double fs = g_sum_f[n * Cc + c];
    float fore = (float)(fe / es + fd / ds);
    float back = (float)((fs - fd) / bs);
    s_back[n][k][c] = back;
    g_dclu[(n * NCk + k) * Cc + c] = fore - back;
    __syncthreads();
    if (t < 64) {
        int nn = t >> 5, cc = t & 31;
        g_base[nn * Cc + cc] = ((s_back[nn][0][cc] + s_back[nn][1][cc]) +
                                (s_back[nn][2][cc] + s_back[nn][3][cc]));
    }
}

// ---------------- quad attention weights (sigmoid of logit diff) ----------------
template <bool STATS>
__device__ __forceinline__ void quad_w(const float* __restrict__ fb, size_t p,
                                       const u64 sd2[4][32],
                                       u64 wA2[4], u64 wB2[4], float wsum[4]) {
    u64 dA[4] = {0,0,0,0}, dB[4] = {0,0,0,0};
#pragma unroll
    for (int c = 0; c < 32; c++) {
        u64 fA, fB;
        ldg2x2(fb + (size_t)c * Pp + p, fA, fB);
#pragma unroll
        for (int k = 0; k < 4; k++) {
            u64 dc = sd2[k][c];
            dA[k] = ffma2(fA, dc, dA[k]);
            dB[k] = ffma2(fB, dc, dB[k]);
        }
    }
#pragma unroll
    for (int k = 0; k < 4; k++) {
        float a0, a1, a2, a3;
        unpack2(dA[k], a0, a1);
        unpack2(dB[k], a2, a3);
        float w0 = sigf(a0), w1 = sigf(a1), w2 = sigf(a2), w3 = sigf(a3);
        wA2[k] = pack2(w0, w1);
        wB2[k] = pack2(w2, w3);
        if (STATS) wsum[k] += (w0 + w1) + (w2 + w3);
    }
}

// ---------------- pass 1: BN statistics (ssq + W0) ----------------
#define K6B 128
#define K6_VOX 8
__global__ void __launch_bounds__(K6B) k6_stats(const float* __restrict__ feat,
                                                const float* __restrict__ kptr) {
    int n = blockIdx.y;
    int t = threadIdx.x;
    __shared__ u64 s_dclu2[4][32];
    __shared__ u64 s_base2[32];
    __shared__ float s_wq[4][32];
    __shared__ float s_w0[4][4];
    {
        float v = g_dclu[n * 128 + t];
        s_dclu2[t >> 5][t & 31] = pack2(v, v);
        if (t < 32) { float b = g_base[n * 32 + t]; s_base2[t] = pack2(b, b); }
    }
    float kk = kptr[0];
    __syncthreads();

    const float* __restrict__ fb = feat + (size_t)n * Cc * Pp;
    const u64 five2 = pack2(5.0f, 5.0f);
    const u64 kk2 = pack2(kk, kk);

    u64 ssq2[32];
#pragma unroll
    for (int c = 0; c < 32; c++) ssq2[c] = 0ull;
    float wsum[4] = {0.f, 0.f, 0.f, 0.f};

    int qbase = blockIdx.x * (K6B * K6_VOX) + t;
    for (int it = 0; it < K6_VOX; it++) {
        size_t p = (size_t)(qbase + it * K6B) * 4;
        u64 wA2[4], wB2[4];
        quad_w<true>(fb, p, s_dclu2, wA2, wB2, wsum);
#pragma unroll
        for (int c = 0; c < 32; c++) {
            u64 fA, fB;
            ldg2x2(fb + (size_t)c * Pp + p, fA, fB);
            u64 aA = s_base2[c], aB = s_base2[c];
#pragma unroll
            for (int k = 0; k < 4; k++) {
                u64 dc = s_dclu2[k][c];
                aA = ffma2(wA2[k], dc, aA);
                aB = ffma2(wB2[k], dc, aB);
            }
            u64 oA = ffma2(fA, five2, fmul2(kk2, aA));
            u64 oB = ffma2(fB, five2, fmul2(kk2, aB));
            ssq2[c] = ffma2(oA, oA, ssq2[c]);
            ssq2[c] = ffma2(oB, oB, ssq2[c]);
        }
    }

    int lane = t & 31, warp = t >> 5;
#pragma unroll
    for (int c = 0; c < 32; c++) {
        float lo, hi;
        unpack2(ssq2[c], lo, hi);
        float q = lo + hi;
#pragma unroll
        for (int o = 16; o; o >>= 1) q += __shfl_down_sync(0xffffffffu, q, o);
        if (lane == 0) s_wq[warp][c] = q;
    }
#pragma unroll
    for (int k = 0; k < 4; k++) {
        float s = wsum[k];
#pragma unroll
        for (int o = 16; o; o >>= 1) s += __shfl_down_sync(0xffffffffu, s, o);
        if (lane == 0) s_w0[warp][k] = s;
    }
    __syncthreads();
    if (t < 32) {
        float q = ((s_wq[0][t] + s_wq[1][t]) + (s_wq[2][t] + s_wq[3][t]));
        atomicAdd(&g_ch_sq[t], (double)q);
    }
    if (t >= 32 && t < 36) {
        int k = t - 32;
        float s = ((s_w0[0][k] + s_w0[1][k]) + (s_w0[2][k] + s_w0[3][k]));
        atomicAdd(&g_W0[n * NCk + k], (double)s);
    }
}

// ---------------- BN scale/shift (analytic mean) ----------------
__global__ void k7_bn(const float* __restrict__ bw, const float* __restrict__ bb,
                      const float* __restrict__ kptr) {
    int c = threadIdx.x;
    if (c < Cc) {
        double kkd = (double)kptr[0];
        double tot = 0.0;
#pragma unroll
        for (int n = 0; n < Nn; n++) {
            double a = (double)Pp * (double)g_base[n * Cc + c];
#pragma unroll
            for (int k = 0; k < 4; k++)
                a += (double)g_dclu[(n * NCk + k) * Cc + c] * g_W0[n * NCk + k];
            tot += 5.0 * g_sum_f[n * Cc + c] + kkd * a;
        }
        double cnt = (double)Nn * (double)Pp;
        double mean = tot / cnt;
        double var = g_ch_sq[c] / cnt - mean * mean;
        double inv = 1.0 / sqrt(var + 1e-5);
        double sc = bw[c] * inv;
        g_scale[c] = (float)sc;
        g_shift[c] = (float)(bb[c] - mean * sc);
    }
}

// ---------------- pass 2: recompute attention + normalize + write ----------------
#define K8B 256
#define K8_VOX 4
__global__ void __launch_bounds__(K8B) k8_out(const float* __restrict__ feat,
                                              const float* __restrict__ kptr,
                                              float* __restrict__ out) {
    int n = blockIdx.y;
    int t = threadIdx.x;
    __shared__ u64 s_dclu2[4][32];
    __shared__ u64 s_base2[32];
    __shared__ u64 s_sc2[32], s_sh2[32];
    if (t < 128) {
        float v = g_dclu[n * 128 + t];
        s_dclu2[t >> 5][t & 31] = pack2(v, v);
    }
    if (t >= 128 && t < 160) {
        int c = t - 128;
        float b = g_base[n * 32 + c];
        s_base2[c] = pack2(b, b);
    }
    if (t >= 160 && t < 192) {
        int c = t - 160;
        s_sc2[c] = pack2(g_scale[c], g_scale[c]);
        s_sh2[c] = pack2(g_shift[c], g_shift[c]);
    }
    float kk = kptr[0];
    __syncthreads();

    const float* __restrict__ fb = feat + (size_t)n * Cc * Pp;
    float* __restrict__ ob = out + (size_t)n * Cc * Pp;
    const u64 five2 = pack2(5.0f, 5.0f);
    const u64 kk2 = pack2(kk, kk);

    int qbase = blockIdx.x * (K8B * K8_VOX) + t;
    for (int it = 0; it < K8_VOX; it++) {
        size_t p = (size_t)(qbase + it * K8B) * 4;
        u64 wA2[4], wB2[4];
        float dummy[4];
        quad_w<false>(fb, p, s_dclu2, wA2, wB2, dummy);
#pragma unroll
        for (int c = 0; c < 32; c++) {
            u64 fA, fB;
            ldg2x2(fb + (size_t)c * Pp + p, fA, fB);
            u64 aA = s_base2[c], aB = s_base2[c];
#pragma unroll
            for (int k = 0; k < 4; k++) {
                u64 dc = s_dclu2[k][c];
                aA = ffma2(wA2[k], dc, aA);
                aB = ffma2(wB2[k], dc, aB);
            }
            u64 oA = ffma2(fA, five2, fmul2(kk2, aA));
            u64 oB = ffma2(fB, five2, fmul2(kk2, aB));
            oA = ffma2(oA, s_sc2[c], s_sh2[c]);
            oB = ffma2(oB, s_sc2[c], s_sh2[c]);
            stg2x2(ob + (size_t)c * Pp + p, oA, oB);
        }
    }
}

// ---------------- launcher ----------------
extern "C" void kernel_launch(void* const* d_in, const int* in_sizes, int n_in,
                              void* d_out, int out_size) {
    const float* feat = nullptr;
    const float* x    = nullptr;
    const float* kp   = nullptr;
    const float* bw   = nullptr;
    const float* bb   = nullptr;
    for (int i = 0; i < n_in; i++) {
        int s = in_sizes[i];
        const float* p = (const float*)d_in[i];
        if (s == NCP)        feat = p;
        else if (s == NNCP)  x = p;
        else if (s == 1)     kp = p;
        else if (s == Cc)    { if (!bw) bw = p; else bb = p; }
    }
    float* out = (float*)d_out;

    k_pool_hw_erode<<<dim3(96, Nn * NCk), 256>>>((const float4*)x);
    k_pool_d<<<(U4v / 2) / 256, 256>>>();
    k4_contract<<<dim3(Pp4 / (32 * K4_ITER), Nn), 512>>>(feat);
    k5_cluster<<<1, 256>>>();
    k6_stats<<<dim3(Pp4 / (K6B * K6_VOX), Nn), K6B>>>(feat, kp);
    k7_bn<<<1, 32>>>(bw, bb, kp);
    k8_out<<<dim3(Pp4 / (K8B * K8_VOX), Nn), K8B>>>(feat, kp, out);
}

// round 15
// speedup vs baseline: 1.0123x; 1.0123x over previous
#include <cuda_runtime.h>
#include <cuda_bf16.h>
#include <math.h>

#define Nn 2
#define Cc 32
#define NCk 4
#define Pp 884736            // 96*96*96
#define Pp4 221184           // Pp/4
#define NNCP 7077888         // Nn*NCk*Pp
#define NNCP4 1769472        // NNCP/4
#define U4v 884736           // NNCP/8 (uint4 bf16x8 units)
#define NCP  56623104        // Nn*Cc*Pp
#define K4_BLOCKS 432        // 216 x 2

#define PINF  __int_as_float(0x7f800000)
#define NINF  __int_as_float(0xff800000)
#define BNEG2 0xFF80FF80u    // bf16x2 {-inf,-inf}

typedef unsigned long long u64;
typedef unsigned int u32;

// ---------------- f32x2 helpers ----------------
__device__ __forceinline__ u64 pack2(float lo, float hi) {
    u64 r; asm("mov.b64 %0,{%1,%2};" : "=l"(r) : "f"(lo), "f"(hi)); return r;
}
__device__ __forceinline__ void unpack2(u64 v, float& lo, float& hi) {
    asm("mov.b64 {%0,%1},%2;" : "=f"(lo), "=f"(hi) : "l"(v));
}
__device__ __forceinline__ u64 ffma2(u64 a, u64 b, u64 c) {
    u64 d; asm("fma.rn.f32x2 %0,%1,%2,%3;" : "=l"(d) : "l"(a), "l"(b), "l"(c)); return d;
}
__device__ __forceinline__ u64 fmul2(u64 a, u64 b) {
    u64 d; asm("mul.rn.f32x2 %0,%1,%2;" : "=l"(d) : "l"(a), "l"(b)); return d;
}
__device__ __forceinline__ void ldg2x2(const float* p, u64& a, u64& b) {
    asm volatile("ld.global.v2.u64 {%0,%1},[%2];" : "=l"(a), "=l"(b) : "l"(p));
}
__device__ __forceinline__ void stg2x2(float* p, u64 a, u64 b) {
    asm volatile("st.global.v2.u64 [%0],{%1,%2};" :: "l"(p), "l"(a), "l"(b) : "memory");
}
__device__ __forceinline__ u32 packbf2(float lo, float hi) {
    u32 r; asm("cvt.rn.bf16x2.f32 %0,%1,%2;" : "=r"(r) : "f"(hi), "f"(lo)); return r;
}
__device__ __forceinline__ void bf4_to_f32x2(uint2 v, u64& A, u64& B) {
    A = pack2(__uint_as_float(v.x << 16), __uint_as_float(v.x & 0xFFFF0000u));
    B = pack2(__uint_as_float(v.y << 16), __uint_as_float(v.y & 0xFFFF0000u));
}
__device__ __forceinline__ u32 bmax2(u32 a, u32 b) {
    __nv_bfloat162 r = __hmax2(*reinterpret_cast<__nv_bfloat162*>(&a),
                               *reinterpret_cast<__nv_bfloat162*>(&b));
    return *reinterpret_cast<u32*>(&r);
}
__device__ __forceinline__ uint4 bmax8(uint4 a, uint4 b) {
    return make_uint4(bmax2(a.x,b.x), bmax2(a.y,b.y), bmax2(a.z,b.z), bmax2(a.w,b.w));
}
__device__ __forceinline__ float sigf(float v) { return 1.0f / (1.0f + __expf(-v)); }

// ---------------- scratch ----------------
__device__ __align__(16) __nv_bfloat16 g_A[NNCP];
__device__ __align__(16) __nv_bfloat16 g_B[NNCP];
__device__ __align__(16) __nv_bfloat16 g_ero[NNCP];

__device__ float  g_parte[6912];
__device__ float  g_partd[1728];
__device__ double g_sum_fe[Nn * NCk * Cc];
__device__ double g_sum_fd[Nn * NCk * Cc];
__device__ double g_sum_f [Nn * Cc];
__device__ double g_ch_sq [Cc];
__device__ double g_W0    [Nn * NCk];
__device__ float  g_dclu[Nn * NCk * Cc];
__device__ float  g_base[Nn * Cc];
__device__ float  g_scale[Cc];
__device__ float  g_shift[Cc];
__device__ u32    g_k4count;

__device__ __forceinline__ float4 vmin4(float4 a, float4 b) {
    return make_float4(fminf(a.x,b.x), fminf(a.y,b.y), fminf(a.z,b.z), fminf(a.w,b.w));
}

// ---------------- fused: h-max pool + full erode + partial ero sums + zeroing ----------------
__global__ void __launch_bounds__(256) k_pool_h_erode(const float4* __restrict__ x4) {
    int i = blockIdx.x * blockDim.x + threadIdx.x;
    int t = threadIdx.x;
    __shared__ float s_red[8];
    if (blockIdx.x == 0) {
        if (t < 256) { g_sum_fe[t] = 0.0; g_sum_fd[t] = 0.0; }
        if (t < 64)  g_sum_f[t] = 0.0;
        if (t < 32)  g_ch_sq[t] = 0.0;
        if (t < 8)   g_W0[t] = 0.0;
        if (t == 0)  g_k4count = 0u;
    }
    int h4 = i % 24;
    int w = (i / 24) % 96;
    int d = (i / 2304) % 96;
    bool hasP = (h4 >= 1), hasN = (h4 <= 22);
    float4 cur = x4[i];
    float4 pv = make_float4(0,0,0,0), nv = make_float4(0,0,0,0);
    if (hasP) pv = x4[i-1];
    if (hasN) nv = x4[i+1];

    {
        float s[12];
        s[0] = hasP ? pv.x : NINF; s[1] = hasP ? pv.y : NINF;
        s[2] = hasP ? pv.z : NINF; s[3] = hasP ? pv.w : NINF;
        s[4]=cur.x; s[5]=cur.y; s[6]=cur.z; s[7]=cur.w;
        s[8] = hasN ? nv.x : NINF; s[9] = hasN ? nv.y : NINF;
        s[10]= hasN ? nv.z : NINF; s[11]= hasN ? nv.w : NINF;
        float o0 = fmaxf(fmaxf(fmaxf(s[2],s[3]), fmaxf(s[4],s[5])), s[6]);
        float o1 = fmaxf(fmaxf(fmaxf(s[3],s[4]), fmaxf(s[5],s[6])), s[7]);
        float o2 = fmaxf(fmaxf(fmaxf(s[4],s[5]), fmaxf(s[6],s[7])), s[8]);
        float o3 = fmaxf(fmaxf(fmaxf(s[5],s[6]), fmaxf(s[7],s[8])), s[9]);
        reinterpret_cast<uint2*>(g_A)[i] = make_uint2(packbf2(o0,o1), packbf2(o2,o3));
    }
    float esum;
    {
        float s[12];
        s[0] = hasP ? pv.x : PINF; s[1] = hasP ? pv.y : PINF;
        s[2] = hasP ? pv.z : PINF; s[3] = hasP ? pv.w : PINF;
        s[4]=cur.x; s[5]=cur.y; s[6]=cur.z; s[7]=cur.w;
        s[8] = hasN ? nv.x : PINF; s[9] = hasN ? nv.y : PINF;
        s[10]= hasN ? nv.z : PINF; s[11]= hasN ? nv.w : PINF;
        float4 m;
        m.x = fminf(fminf(fminf(s[2],s[3]), fminf(s[4],s[5])), s[6]);
        m.y = fminf(fminf(fminf(s[3],s[4]), fminf(s[5],s[6])), s[7]);
        m.z = fminf(fminf(fminf(s[4],s[5]), fminf(s[6],s[7])), s[8]);
        m.w = fminf(fminf(fminf(s[5],s[6]), fminf(s[7],s[8])), s[9]);
        if (w >= 1)  m = vmin4(m, x4[i - 24]);
        if (w >= 2)  m = vmin4(m, x4[i - 48]);
        if (w <= 94) m = vmin4(m, x4[i + 24]);
        if (w <= 93) m = vmin4(m, x4[i + 48]);
        if (d >= 1)  m = vmin4(m, x4[i - 2304]);
        if (d >= 2)  m = vmin4(m, x4[i - 4608]);
        if (d <= 94) m = vmin4(m, x4[i + 2304]);
        if (d <= 93) m = vmin4(m, x4[i + 4608]);
        m.x = sigf(m.x); m.y = sigf(m.y); m.z = sigf(m.z); m.w = sigf(m.w);
        reinterpret_cast<uint2*>(g_ero)[i] = make_uint2(packbf2(m.x,m.y), packbf2(m.z,m.w));
        esum = (m.x + m.y) + (m.z + m.w);
    }
#pragma unroll
    for (int o = 16; o; o >>= 1) esum += __shfl_down_sync(0xffffffffu, esum, o);
    if ((t & 31) == 0) s_red[t >> 5] = esum;
    __syncthreads();
    if (t == 0) {
        float bsum = 0.f;
#pragma unroll
        for (int wv = 0; wv < 8; wv++) bsum += s_red[wv];
        g_parte[blockIdx.x] = bsum;
    }
}

// ---------------- pool along W (bf16 uint4 = 8 voxels), paired, g_A -> g_B ----------------
__global__ void __launch_bounds__(256) k_pool_w() {
    int j = blockIdx.x * blockDim.x + threadIdx.x;
    const uint4* __restrict__ in = reinterpret_cast<const uint4*>(g_A);
    uint4* __restrict__ outp = reinterpret_cast<uint4*>(g_B);
    int h  = j % 12;
    int wp = (j / 12) % 48;
    int rest = j / 576;
    int i0 = rest * 1152 + wp * 24 + h;
    const uint4 NEG = make_uint4(BNEG2, BNEG2, BNEG2, BNEG2);
    uint4 c0 = in[i0];
    uint4 p1 = in[i0 + 12];
    uint4 m1 = (wp >= 1) ? in[i0 - 12] : NEG;
    uint4 m2 = (wp >= 1) ? in[i0 - 24] : NEG;
    uint4 p2 = (wp <= 46) ? in[i0 + 24] : NEG;
    uint4 p3 = (wp <= 46) ? in[i0 + 36] : NEG;
    outp[i0]      = bmax8(bmax8(bmax8(m2, m1), bmax8(c0, p1)), p2);
    outp[i0 + 12] = bmax8(bmax8(bmax8(m1, c0), bmax8(p1, p2)), p3);
}

// ---------------- pool along D (bf16), paired + sigmoid + partial dil sums ----------------
__device__ __forceinline__ u32 sig_bf2(u32 bits, float& acc) {
    float f0 = sigf(__uint_as_float(bits << 16));
    float f1 = sigf(__uint_as_float(bits & 0xFFFF0000u));
    acc += f0 + f1;
    return packbf2(f0, f1);
}
__global__ void __launch_bounds__(256) k_pool_d() {
    int j = blockIdx.x * blockDim.x + threadIdx.x;
    int t = threadIdx.x;
    __shared__ float s_red[8];
    const uint4* __restrict__ in = reinterpret_cast<const uint4*>(g_B);
    uint4* __restrict__ outp = reinterpret_cast<uint4*>(g_A);
    int hh = j % 1152;
    int dp = (j / 1152) % 48;
    int nk = j / 55296;
    int i0 = nk * 110592 + dp * 2304 + hh;
    const uint4 NEG = make_uint4(BNEG2, BNEG2, BNEG2, BNEG2);
    uint4 c0 = in[i0];
    uint4 p1 = in[i0 + 1152];
    uint4 m1 = (dp >= 1) ? in[i0 - 1152] : NEG;
    uint4 m2 = (dp >= 1) ? in[i0 - 2304] : NEG;
    uint4 p2 = (dp <= 46) ? in[i0 + 2304] : NEG;
    uint4 p3 = (dp <= 46) ? in[i0 + 3456] : NEG;
    uint4 o0 = bmax8(bmax8(bmax8(m2, m1), bmax8(c0, p1)), p2);
    uint4 o1 = bmax8(bmax8(bmax8(m1, c0), bmax8(p1, p2)), p3);
    float dsum = 0.f;
    o0.x = sig_bf2(o0.x, dsum); o0.y = sig_bf2(o0.y, dsum);
    o0.z = sig_bf2(o0.z, dsum); o0.w = sig_bf2(o0.w, dsum);
    o1.x = sig_bf2(o1.x, dsum); o1.y = sig_bf2(o1.y, dsum);
    o1.z = sig_bf2(o1.z, dsum); o1.w = sig_bf2(o1.w, dsum);
    outp[i0] = o0;
    outp[i0 + 1152] = o1;
#pragma unroll
    for (int o = 16; o; o >>= 1) dsum += __shfl_down_sync(0xffffffffu, dsum, o);
    if ((t & 31) == 0) s_red[t >> 5] = dsum;
    __syncthreads();
    if (t == 0) {
        float bsum = 0.f;
#pragma unroll
        for (int wv = 0; wv < 8; wv++) bsum += s_red[wv];
        g_partd[blockIdx.x] = bsum;
    }
}

// ---------------- contraction (bf16 masks, double-buffered) + last-block cluster build ----------------
#define K4_ITER 32
__device__ __forceinline__ void k4_loadED(const __nv_bfloat16* __restrict__ eb,
                                          const __nv_bfloat16* __restrict__ db,
                                          size_t p, uint2 ev[4], uint2 dv[4]) {
#pragma unroll
    for (int k = 0; k < 4; k++) {
        ev[k] = *reinterpret_cast<const uint2*>(eb + (size_t)k * Pp + p);
        dv[k] = *reinterpret_cast<const uint2*>(db + (size_t)k * Pp + p);
    }
}
__device__ __forceinline__ void k4_body(const float* __restrict__ fb, int c0, size_t p,
                                        const uint2 ev[4], const uint2 dv[4],
                                        u64 acc_e[2][4], u64 acc_d[2][4], u64 accf[2], u64 one2) {
    u64 fA0, fB0, fA1, fB1;
    ldg2x2(fb + (size_t)c0 * Pp + p, fA0, fB0);
    ldg2x2(fb + (size_t)(c0 + 1) * Pp + p, fA1, fB1);
    u64 eA[4], eB[4], dA[4], dB[4];
#pragma unroll
    for (int k = 0; k < 4; k++) {
        bf4_to_f32x2(ev[k], eA[k], eB[k]);
        bf4_to_f32x2(dv[k], dA[k], dB[k]);
    }
    accf[0] = ffma2(fA0, one2, accf[0]); accf[0] = ffma2(fB0, one2, accf[0]);
    accf[1] = ffma2(fA1, one2, accf[1]); accf[1] = ffma2(fB1, one2, accf[1]);
#pragma unroll
    for (int k = 0; k < 4; k++) {
        acc_e[0][k] = ffma2(fA0, eA[k], acc_e[0][k]);
        acc_e[0][k] = ffma2(fB0, eB[k], acc_e[0][k]);
        acc_d[0][k] = ffma2(fA0, dA[k], acc_d[0][k]);
        acc_d[0][k] = ffma2(fB0, dB[k], acc_d[0][k]);
        acc_e[1][k] = ffma2(fA1, eA[k], acc_e[1][k]);
        acc_e[1][k] = ffma2(fB1, eB[k], acc_e[1][k]);
        acc_d[1][k] = ffma2(fA1, dA[k], acc_d[1][k]);
        acc_d[1][k] = ffma2(fB1, dB[k], acc_d[1][k]);
    }
}
__global__ void __launch_bounds__(512, 1) k4_contract(const float* __restrict__ feat) {
    int n = blockIdx.y;
    int warp = threadIdx.x >> 5;
    int lane = threadIdx.x & 31;
    int c0 = warp * 2;
    int q0 = blockIdx.x * (32 * K4_ITER) + lane;

    const float* __restrict__ fb = feat + (size_t)n * Cc * Pp;
    const __nv_bfloat16* __restrict__ eb = g_ero + (size_t)n * NCk * Pp;
    const __nv_bfloat16* __restrict__ db = g_A   + (size_t)n * NCk * Pp;

    u64 acc_e[2][4], acc_d[2][4], accf[2];
#pragma unroll
    for (int j = 0; j < 2; j++) {
        accf[j] = 0ull;
#pragma unroll
        for (int k = 0; k < 4; k++) { acc_e[j][k] = 0ull; acc_d[j][k] = 0ull; }
    }
    const u64 one2 = pack2(1.0f, 1.0f);

    uint2 e0[4], d0[4], e1[4], d1[4];
    size_t p = (size_t)q0 * 4;
    k4_loadED(eb, db, p, e0, d0);
    for (int i = 0; i < K4_ITER; i += 2) {
        size_t pn = p + 128;
        k4_loadED(eb, db, pn, e1, d1);
        k4_body(fb, c0, p, e0, d0, acc_e, acc_d, accf, one2);
        size_t pn2 = p + 256;
        if (i + 2 < K4_ITER) k4_loadED(eb, db, pn2, e0, d0);
        k4_body(fb, c0, pn, e1, d1, acc_e, acc_d, accf, one2);
        p = pn2;
    }

#pragma unroll
    for (int j = 0; j < 2; j++) {
#pragma unroll
        for (int k = 0; k < 4; k++) {
            float l0, h0, l1, h1;
            unpack2(acc_e[j][k], l0, h0);
            unpack2(acc_d[j][k], l1, h1);
            float ae = l0 + h0, ad = l1 + h1;
#pragma unroll
            for (int o = 16; o; o >>= 1) {
                ae += __shfl_down_sync(0xffffffffu, ae, o);
                ad += __shfl_down_sync(0xffffffffu, ad, o);
            }
            if (lane == 0) {
                atomicAdd(&g_sum_fe[(n * NCk + k) * Cc + c0 + j], (double)ae);
                atomicAdd(&g_sum_fd[(n * NCk + k) * Cc + c0 + j], (double)ad);
            }
        }
        float lf, hf;
        unpack2(accf[j], lf, hf);
        float af = lf + hf;
#pragma unroll
        for (int o = 16; o; o >>= 1) af += __shfl_down_sync(0xffffffffu, af, o);
        if (lane == 0) atomicAdd(&g_sum_f[n * Cc + c0 + j], (double)af);
    }

    // ---- last-block-done: fold cluster build into k4 tail ----
    __shared__ u32 s_last;
    __shared__ float s_back[Nn][NCk][Cc];
    __shared__ double s_se[8], s_sd[8];
    __threadfence();
    __syncthreads();
    if (threadIdx.x == 0) {
        u32 prev = atomicAdd(&g_k4count, 1u);
        s_last = (prev == (u32)(K4_BLOCKS - 1)) ? 1u : 0u;
    }
    __syncthreads();
    if (!s_last) return;

    int t = threadIdx.x;
    if (t < 256) {
        int w8 = t >> 5, l = t & 31;
        double se = 0.0;
        for (int j = l; j < 864; j += 32) se += (double)g_parte[w8 * 864 + j];
        double sd = 0.0;
        for (int j = l; j < 216; j += 32) sd += (double)g_partd[w8 * 216 + j];
#pragma unroll
        for (int o = 16; o; o >>= 1) {
            se += __shfl_down_sync(0xffffffffu, se, o);
            sd += __shfl_down_sync(0xffffffffu, sd, o);
        }
        if (l == 0) { s_se[w8] = se; s_sd[w8] = sd; }
    }
    __syncthreads();
    if (t < 256) {
        int nn = t >> 7;
        int k = (t >> 5) & 3;
        int c = t & 31;
        double es = s_se[nn * NCk + k] + 1e-5;
        double ds = s_sd[nn * NCk + k] + 1e-5;
        double bs = (double)Pp - s_sd[nn * NCk + k] + 1e-5;
        double fe = g_sum_fe[(nn * NCk + k) * Cc + c];
        double fd = g_sum_fd[(nn * NCk + k) * Cc + c];
        double fs = g_sum_f[nn * Cc + c];
        float fore = (float)(fe / es + fd / ds);
        float back = (float)((fs - fd) / bs);
        s_back[nn][k][c] = back;
        g_dclu[(nn * NCk + k) * Cc + c] = fore - back;
    }
    __syncthreads();
    if (t < 64) {
        int nn = t >> 5, cc = t & 31;
        g_base[nn * Cc + cc] = ((s_back[nn][0][cc] + s_back[nn][1][cc]) +
                                (s_back[nn][2][cc] + s_back[nn][3][cc]));
    }
}

// ---------------- quad attention weights (sigmoid of logit diff) ----------------
template <bool STATS>
__device__ __forceinline__ void quad_w(const float* __restrict__ fb, size_t p,
                                       const u64 sd2[4][32],
                                       u64 wA2[4], u64 wB2[4], float wsum[4]) {
    u64 dA[4] = {0,0,0,0}, dB[4] = {0,0,0,0};
#pragma unroll
    for (int c = 0; c < 32; c++) {
        u64 fA, fB;
        ldg2x2(fb + (size_t)c * Pp + p, fA, fB);
#pragma unroll
        for (int k = 0; k < 4; k++) {
            u64 dc = sd2[k][c];
            dA[k] = ffma2(fA, dc, dA[k]);
            dB[k] = ffma2(fB, dc, dB[k]);
        }
    }
#pragma unroll
    for (int k = 0; k < 4; k++) {
        float a0, a1, a2, a3;
        unpack2(dA[k], a0, a1);
        unpack2(dB[k], a2, a3);
        float w0 = sigf(a0), w1 = sigf(a1), w2 = sigf(a2), w3 = sigf(a3);
        wA2[k] = pack2(w0, w1);
        wB2[k] = pack2(w2, w3);
        if (STATS) wsum[k] += (w0 + w1) + (w2 + w3);
    }
}

// ---------------- pass 1: BN statistics (ssq + W0) ----------------
#define K6B 128
#define K6_VOX 8
__global__ void __launch_bounds__(K6B) k6_stats(const float* __restrict__ feat,
                                                const float* __restrict__ kptr) {
    int n = blockIdx.y;
    int t = threadIdx.x;
    __shared__ u64 s_dclu2[4][32];
    __shared__ u64 s_base2[32];
    __shared__ float s_wq[4][32];
    __shared__ float s_w0[4][4];
    {
        float v = g_dclu[n * 128 + t];
        s_dclu2[t >> 5][t & 31] = pack2(v, v);
        if (t < 32) { float b = g_base[n * 32 + t]; s_base2[t] = pack2(b, b); }
    }
    float kk = kptr[0];
    __syncthreads();

    const float* __restrict__ fb = feat + (size_t)n * Cc * Pp;
    const u64 five2 = pack2(5.0f, 5.0f);
    const u64 kk2 = pack2(kk, kk);

    u64 ssq2[32];
#pragma unroll
    for (int c = 0; c < 32; c++) ssq2[c] = 0ull;
    float wsum[4] = {0.f, 0.f, 0.f, 0.f};

    int qbase = blockIdx.x * (K6B * K6_VOX) + t;
    for (int it = 0; it < K6_VOX; it++) {
        size_t p = (size_t)(qbase + it * K6B) * 4;
        u64 wA2[4], wB2[4];
        quad_w<true>(fb, p, s_dclu2, wA2, wB2, wsum);
#pragma unroll
        for (int c = 0; c < 32; c++) {
            u64 fA, fB;
            ldg2x2(fb + (size_t)c * Pp + p, fA, fB);
            u64 aA = s_base2[c], aB = s_base2[c];
#pragma unroll
            for (int k = 0; k < 4; k++) {
                u64 dc = s_dclu2[k][c];
                aA = ffma2(wA2[k], dc, aA);
                aB = ffma2(wB2[k], dc, aB);
            }
            u64 oA = ffma2(fA, five2, fmul2(kk2, aA));
            u64 oB = ffma2(fB, five2, fmul2(kk2, aB));
            ssq2[c] = ffma2(oA, oA, ssq2[c]);
            ssq2[c] = ffma2(oB, oB, ssq2[c]);
        }
    }

    int lane = t & 31, warp = t >> 5;
#pragma unroll
    for (int c = 0; c < 32; c++) {
        float lo, hi;
        unpack2(ssq2[c], lo, hi);
        float q = lo + hi;
#pragma unroll
        for (int o = 16; o; o >>= 1) q += __shfl_down_sync(0xffffffffu, q, o);
        if (lane == 0) s_wq[warp][c] = q;
    }
#pragma unroll
    for (int k = 0; k < 4; k++) {
        float s = wsum[k];
#pragma unroll
        for (int o = 16; o; o >>= 1) s += __shfl_down_sync(0xffffffffu, s, o);
        if (lane == 0) s_w0[warp][k] = s;
    }
    __syncthreads();
    if (t < 32) {
        float q = ((s_wq[0][t] + s_wq[1][t]) + (s_wq[2][t] + s_wq[3][t]));
        atomicAdd(&g_ch_sq[t], (double)q);
    }
    if (t >= 32 && t < 36) {
        int k = t - 32;
        float s = ((s_w0[0][k] + s_w0[1][k]) + (s_w0[2][k] + s_w0[3][k]));
        atomicAdd(&g_W0[n * NCk + k], (double)s);
    }
}

// ---------------- BN scale/shift (analytic mean) ----------------
__global__ void k7_bn(const float* __restrict__ bw, const float* __restrict__ bb,
                      const float* __restrict__ kptr) {
    int c = threadIdx.x;
    if (c < Cc) {
        double kkd = (double)kptr[0];
        double tot = 0.0;
#pragma unroll
        for (int n = 0; n < Nn; n++) {
            double a = (double)Pp * (double)g_base[n * Cc + c];
#pragma unroll
            for (int k = 0; k < 4; k++)
                a += (double)g_dclu[(n * NCk + k) * Cc + c] * g_W0[n * NCk + k];
            tot += 5.0 * g_sum_f[n * Cc + c] + kkd * a;
        }
        double cnt = (double)Nn * (double)Pp;
        double mean = tot / cnt;
        double var = g_ch_sq[c] / cnt - mean * mean;
        double inv = 1.0 / sqrt(var + 1e-5);
        double sc = bw[c] * inv;
        g_scale[c] = (float)sc;
        g_shift[c] = (float)(bb[c] - mean * sc);
    }
}

// ---------------- pass 2: recompute attention + normalize + write ----------------
#define K8B 256
#define K8_VOX 4
__global__ void __launch_bounds__(K8B) k8_out(const float* __restrict__ feat,
                                              const float* __restrict__ kptr,
                                              float* __restrict__ out) {
    int n = blockIdx.y;
    int t = threadIdx.x;
    __shared__ u64 s_dclu2[4][32];
    __shared__ u64 s_base2[32];
    __shared__ u64 s_sc2[32], s_sh2[32];
    if (t < 128) {
        float v = g_dclu[n * 128 + t];
        s_dclu2[t >> 5][t & 31] = pack2(v, v);
    }
    if (t >= 128 && t < 160) {
        int c = t - 128;
        float b = g_base[n * 32 + c];
        s_base2[c] = pack2(b, b);
    }
    if (t >= 160 && t < 192) {
        int c = t - 160;
        s_sc2[c] = pack2(g_scale[c], g_scale[c]);
        s_sh2[c] = pack2(g_shift[c], g_shift[c]);
    }
    float kk = kptr[0];
    __syncthreads();

    const float* __restrict__ fb = feat + (size_t)n * Cc * Pp;
    float* __restrict__ ob = out + (size_t)n * Cc * Pp;
    const u64 five2 = pack2(5.0f, 5.0f);
    const u64 kk2 = pack2(kk, kk);

    int qbase = blockIdx.x * (K8B * K8_VOX) + t;
    for (int it = 0; it < K8_VOX; it++) {
        size_t p = (size_t)(qbase + it * K8B) * 4;
        u64 wA2[4], wB2[4];
        float dummy[4];
        quad_w<false>(fb, p, s_dclu2, wA2, wB2, dummy);
#pragma unroll
        for (int c = 0; c < 32; c++) {
            u64 fA, fB;
            ldg2x2(fb + (size_t)c * Pp + p, fA, fB);
            u64 aA = s_base2[c], aB = s_base2[c];
#pragma unroll
            for (int k = 0; k < 4; k++) {
                u64 dc = s_dclu2[k][c];
                aA = ffma2(wA2[k], dc, aA);
                aB = ffma2(wB2[k], dc, aB);
            }
            u64 oA = ffma2(fA, five2, fmul2(kk2, aA));
            u64 oB = ffma2(fB, five2, fmul2(kk2, aB));
            oA = ffma2(oA, s_sc2[c], s_sh2[c]);
            oB = ffma2(oB, s_sc2[c], s_sh2[c]);
            stg2x2(ob + (size_t)c * Pp + p, oA, oB);
        }
    }
}

// ---------------- launcher ----------------
extern "C" void kernel_launch(void* const* d_in, const int* in_sizes, int n_in,
                              void* d_out, int out_size) {
    const float* feat = nullptr;
    const float* x    = nullptr;
    const float* kp   = nullptr;
    const float* bw   = nullptr;
    const float* bb   = nullptr;
    for (int i = 0; i < n_in; i++) {
        int s = in_sizes[i];
        const float* p = (const float*)d_in[i];
        if (s == NCP)        feat = p;
        else if (s == NNCP)  x = p;
        else if (s == 1)     kp = p;
        else if (s == Cc)    { if (!bw) bw = p; else bb = p; }
    }
    float* out = (float*)d_out;

    k_pool_h_erode<<<NNCP4 / 256, 256>>>((const float4*)x);
    k_pool_w<<<(U4v / 2) / 256, 256>>>();
    k_pool_d<<<(U4v / 2) / 256, 256>>>();
    k4_contract<<<dim3(Pp4 / (32 * K4_ITER), Nn), 512>>>(feat);   // includes cluster build in last block
    k6_stats<<<dim3(Pp4 / (K6B * K6_VOX), Nn), K6B>>>(feat, kp);
    k7_bn<<<1, 32>>>(bw, bb, kp);
    k8_out<<<dim3(Pp4 / (K8B * K8_VOX), Nn), K8B>>>(feat, kp, out);
}

// round 16
// speedup vs baseline: 1.0446x; 1.0318x over previous
#include <cuda_runtime.h>
#include <cuda_bf16.h>
#include <math.h>

#define Nn 2
#define Cc 32
#define NCk 4
#define Pp 884736            // 96*96*96
#define Pp4 221184           // Pp/4
#define NNCP 7077888         // Nn*NCk*Pp
#define NNCP4 1769472        // NNCP/4
#define U4v 884736           // NNCP/8 (uint4 bf16x8 units)
#define NCP  56623104        // Nn*Cc*Pp

#define PINF  __int_as_float(0x7f800000)
#define NINF  __int_as_float(0xff800000)
#define BNEG2 0xFF80FF80u    // bf16x2 {-inf,-inf}

typedef unsigned long long u64;
typedef unsigned int u32;

// ---------------- f32x2 helpers ----------------
__device__ __forceinline__ u64 pack2(float lo, float hi) {
    u64 r; asm("mov.b64 %0,{%1,%2};" : "=l"(r) : "f"(lo), "f"(hi)); return r;
}
__device__ __forceinline__ void unpack2(u64 v, float& lo, float& hi) {
    asm("mov.b64 {%0,%1},%2;" : "=f"(lo), "=f"(hi) : "l"(v));
}
__device__ __forceinline__ u64 ffma2(u64 a, u64 b, u64 c) {
    u64 d; asm("fma.rn.f32x2 %0,%1,%2,%3;" : "=l"(d) : "l"(a), "l"(b), "l"(c)); return d;
}
__device__ __forceinline__ u64 fmul2(u64 a, u64 b) {
    u64 d; asm("mul.rn.f32x2 %0,%1,%2;" : "=l"(d) : "l"(a), "l"(b)); return d;
}
__device__ __forceinline__ void ldg2x2(const float* p, u64& a, u64& b) {
    asm volatile("ld.global.v2.u64 {%0,%1},[%2];" : "=l"(a), "=l"(b) : "l"(p));
}
__device__ __forceinline__ void stg2x2(float* p, u64 a, u64 b) {
    asm volatile("st.global.v2.u64 [%0],{%1,%2};" :: "l"(p), "l"(a), "l"(b) : "memory");
}
__device__ __forceinline__ u32 packbf2(float lo, float hi) {
    u32 r; asm("cvt.rn.bf16x2.f32 %0,%1,%2;" : "=r"(r) : "f"(hi), "f"(lo)); return r;
}
__device__ __forceinline__ void bf4_to_f32x2(uint2 v, u64& A, u64& B) {
    A = pack2(__uint_as_float(v.x << 16), __uint_as_float(v.x & 0xFFFF0000u));
    B = pack2(__uint_as_float(v.y << 16), __uint_as_float(v.y & 0xFFFF0000u));
}
__device__ __forceinline__ u32 bmax2(u32 a, u32 b) {
    __nv_bfloat162 r = __hmax2(*reinterpret_cast<__nv_bfloat162*>(&a),
                               *reinterpret_cast<__nv_bfloat162*>(&b));
    return *reinterpret_cast<u32*>(&r);
}
__device__ __forceinline__ uint4 bmax8(uint4 a, uint4 b) {
    return make_uint4(bmax2(a.x,b.x), bmax2(a.y,b.y), bmax2(a.z,b.z), bmax2(a.w,b.w));
}
__device__ __forceinline__ float sigf(float v) { return 1.0f / (1.0f + __expf(-v)); }

// ---------------- scratch ----------------
__device__ __align__(16) __nv_bfloat16 g_A[NNCP];
__device__ __align__(16) __nv_bfloat16 g_B[NNCP];
__device__ __align__(16) __nv_bfloat16 g_ero[NNCP];

__device__ float  g_parte[6912];
__device__ float  g_partd[1728];
__device__ double g_sum_fe[Nn * NCk * Cc];
__device__ double g_sum_fd[Nn * NCk * Cc];
__device__ double g_sum_f [Nn * Cc];
__device__ double g_ch_sq [Cc];
__device__ double g_W0    [Nn * NCk];
__device__ float  g_dclu[Nn * NCk * Cc];
__device__ float  g_base[Nn * Cc];
__device__ float  g_scale[Cc];
__device__ float  g_shift[Cc];

__device__ __forceinline__ float4 vmin4(float4 a, float4 b) {
    return make_float4(fminf(a.x,b.x), fminf(a.y,b.y), fminf(a.z,b.z), fminf(a.w,b.w));
}

// ---------------- fused: h-max pool + full erode + partial ero sums + zeroing ----------------
__global__ void __launch_bounds__(256) k_pool_h_erode(const float4* __restrict__ x4) {
    int i = blockIdx.x * blockDim.x + threadIdx.x;
    int t = threadIdx.x;
    __shared__ float s_red[8];
    if (blockIdx.x == 0) {
        if (t < 256) { g_sum_fe[t] = 0.0; g_sum_fd[t] = 0.0; }
        if (t < 64)  g_sum_f[t] = 0.0;
        if (t < 32)  g_ch_sq[t] = 0.0;
        if (t < 8)   g_W0[t] = 0.0;
    }
    int h4 = i % 24;
    int w = (i / 24) % 96;
    int d = (i / 2304) % 96;
    bool hasP = (h4 >= 1), hasN = (h4 <= 22);
    float4 cur = x4[i];
    float4 pv = make_float4(0,0,0,0), nv = make_float4(0,0,0,0);
    if (hasP) pv = x4[i-1];
    if (hasN) nv = x4[i+1];

    {
        float s[12];
        s[0] = hasP ? pv.x : NINF; s[1] = hasP ? pv.y : NINF;
        s[2] = hasP ? pv.z : NINF; s[3] = hasP ? pv.w : NINF;
        s[4]=cur.x; s[5]=cur.y; s[6]=cur.z; s[7]=cur.w;
        s[8] = hasN ? nv.x : NINF; s[9] = hasN ? nv.y : NINF;
        s[10]= hasN ? nv.z : NINF; s[11]= hasN ? nv.w : NINF;
        float o0 = fmaxf(fmaxf(fmaxf(s[2],s[3]), fmaxf(s[4],s[5])), s[6]);
        float o1 = fmaxf(fmaxf(fmaxf(s[3],s[4]), fmaxf(s[5],s[6])), s[7]);
        float o2 = fmaxf(fmaxf(fmaxf(s[4],s[5]), fmaxf(s[6],s[7])), s[8]);
        float o3 = fmaxf(fmaxf(fmaxf(s[5],s[6]), fmaxf(s[7],s[8])), s[9]);
        reinterpret_cast<uint2*>(g_A)[i] = make_uint2(packbf2(o0,o1), packbf2(o2,o3));
    }
    float esum;
    {
        float s[12];
        s[0] = hasP ? pv.x : PINF; s[1] = hasP ? pv.y : PINF;
        s[2] = hasP ? pv.z : PINF; s[3] = hasP ? pv.w : PINF;
        s[4]=cur.x; s[5]=cur.y; s[6]=cur.z; s[7]=cur.w;
        s[8] = hasN ? nv.x : PINF; s[9] = hasN ? nv.y : PINF;
        s[10]= hasN ? nv.z : PINF; s[11]= hasN ? nv.w : PINF;
        float4 m;
        m.x = fminf(fminf(fminf(s[2],s[3]), fminf(s[4],s[5])), s[6]);
        m.y = fminf(fminf(fminf(s[3],s[4]), fminf(s[5],s[6])), s[7]);
        m.z = fminf(fminf(fminf(s[4],s[5]), fminf(s[6],s[7])), s[8]);
        m.w = fminf(fminf(fminf(s[5],s[6]), fminf(s[7],s[8])), s[9]);
        if (w >= 1)  m = vmin4(m, x4[i - 24]);
        if (w >= 2)  m = vmin4(m, x4[i - 48]);
        if (w <= 94) m = vmin4(m, x4[i + 24]);
        if (w <= 93) m = vmin4(m, x4[i + 48]);
        if (d >= 1)  m = vmin4(m, x4[i - 2304]);
        if (d >= 2)  m = vmin4(m, x4[i - 4608]);
        if (d <= 94) m = vmin4(m, x4[i + 2304]);
        if (d <= 93) m = vmin4(m, x4[i + 4608]);
        m.x = sigf(m.x); m.y = sigf(m.y); m.z = sigf(m.z); m.w = sigf(m.w);
        reinterpret_cast<uint2*>(g_ero)[i] = make_uint2(packbf2(m.x,m.y), packbf2(m.z,m.w));
        esum = (m.x + m.y) + (m.z + m.w);
    }
#pragma unroll
    for (int o = 16; o; o >>= 1) esum += __shfl_down_sync(0xffffffffu, esum, o);
    if ((t & 31) == 0) s_red[t >> 5] = esum;
    __syncthreads();
    if (t == 0) {
        float bsum = 0.f;
#pragma unroll
        for (int wv = 0; wv < 8; wv++) bsum += s_red[wv];
        g_parte[blockIdx.x] = bsum;
    }
}

// ---------------- pool along W (bf16 uint4 = 8 voxels), paired, g_A -> g_B ----------------
__global__ void __launch_bounds__(256) k_pool_w() {
    int j = blockIdx.x * blockDim.x + threadIdx.x;
    const uint4* __restrict__ in = reinterpret_cast<const uint4*>(g_A);
    uint4* __restrict__ outp = reinterpret_cast<uint4*>(g_B);
    int h  = j % 12;
    int wp = (j / 12) % 48;
    int rest = j / 576;
    int i0 = rest * 1152 + wp * 24 + h;
    const uint4 NEG = make_uint4(BNEG2, BNEG2, BNEG2, BNEG2);
    uint4 c0 = in[i0];
    uint4 p1 = in[i0 + 12];
    uint4 m1 = (wp >= 1) ? in[i0 - 12] : NEG;
    uint4 m2 = (wp >= 1) ? in[i0 - 24] : NEG;
    uint4 p2 = (wp <= 46) ? in[i0 + 24] : NEG;
    uint4 p3 = (wp <= 46) ? in[i0 + 36] : NEG;
    outp[i0]      = bmax8(bmax8(bmax8(m2, m1), bmax8(c0, p1)), p2);
    outp[i0 + 12] = bmax8(bmax8(bmax8(m1, c0), bmax8(p1, p2)), p3);
}

// ---------------- pool along D (bf16), paired + sigmoid + partial dil sums ----------------
__device__ __forceinline__ u32 sig_bf2(u32 bits, float& acc) {
    float f0 = sigf(__uint_as_float(bits << 16));
    float f1 = sigf(__uint_as_float(bits & 0xFFFF0000u));
    acc += f0 + f1;
    return packbf2(f0, f1);
}
__global__ void __launch_bounds__(256) k_pool_d() {
    int j = blockIdx.x * blockDim.x + threadIdx.x;
    int t = threadIdx.x;
    __shared__ float s_red[8];
    const uint4* __restrict__ in = reinterpret_cast<const uint4*>(g_B);
    uint4* __restrict__ outp = reinterpret_cast<uint4*>(g_A);
    int hh = j % 1152;
    int dp = (j / 1152) % 48;
    int nk = j / 55296;
    int i0 = nk * 110592 + dp * 2304 + hh;
    const uint4 NEG = make_uint4(BNEG2, BNEG2, BNEG2, BNEG2);
    uint4 c0 = in[i0];
    uint4 p1 = in[i0 + 1152];
    uint4 m1 = (dp >= 1) ? in[i0 - 1152] : NEG;
    uint4 m2 = (dp >= 1) ? in[i0 - 2304] : NEG;
    uint4 p2 = (dp <= 46) ? in[i0 + 2304] : NEG;
    uint4 p3 = (dp <= 46) ? in[i0 + 3456] : NEG;
    uint4 o0 = bmax8(bmax8(bmax8(m2, m1), bmax8(c0, p1)), p2);
    uint4 o1 = bmax8(bmax8(bmax8(m1, c0), bmax8(p1, p2)), p3);
    float dsum = 0.f;
    o0.x = sig_bf2(o0.x, dsum); o0.y = sig_bf2(o0.y, dsum);
    o0.z = sig_bf2(o0.z, dsum); o0.w = sig_bf2(o0.w, dsum);
    o1.x = sig_bf2(o1.x, dsum); o1.y = sig_bf2(o1.y, dsum);
    o1.z = sig_bf2(o1.z, dsum); o1.w = sig_bf2(o1.w, dsum);
    outp[i0] = o0;
    outp[i0 + 1152] = o1;
#pragma unroll
    for (int o = 16; o; o >>= 1) dsum += __shfl_down_sync(0xffffffffu, dsum, o);
    if ((t & 31) == 0) s_red[t >> 5] = dsum;
    __syncthreads();
    if (t == 0) {
        float bsum = 0.f;
#pragma unroll
        for (int wv = 0; wv < 8; wv++) bsum += s_red[wv];
        g_partd[blockIdx.x] = bsum;
    }
}

// ---------------- contraction (bf16 masks, double-buffered) ----------------
#define K4_ITER 32
__device__ __forceinline__ void k4_loadED(const __nv_bfloat16* __restrict__ eb,
                                          const __nv_bfloat16* __restrict__ db,
                                          size_t p, uint2 ev[4], uint2 dv[4]) {
#pragma unroll
    for (int k = 0; k < 4; k++) {
        ev[k] = *reinterpret_cast<const uint2*>(eb + (size_t)k * Pp + p);
        dv[k] = *reinterpret_cast<const uint2*>(db + (size_t)k * Pp + p);
    }
}
__device__ __forceinline__ void k4_body(const float* __restrict__ fb, int c0, size_t p,
                                        const uint2 ev[4], const uint2 dv[4],
                                        u64 acc_e[2][4], u64 acc_d[2][4], u64 accf[2], u64 one2) {
    u64 fA0, fB0, fA1, fB1;
    ldg2x2(fb + (size_t)c0 * Pp + p, fA0, fB0);
    ldg2x2(fb + (size_t)(c0 + 1) * Pp + p, fA1, fB1);
    u64 eA[4], eB[4], dA[4], dB[4];
#pragma unroll
    for (int k = 0; k < 4; k++) {
        bf4_to_f32x2(ev[k], eA[k], eB[k]);
        bf4_to_f32x2(dv[k], dA[k], dB[k]);
    }
    accf[0] = ffma2(fA0, one2, accf[0]); accf[0] = ffma2(fB0, one2, accf[0]);
    accf[1] = ffma2(fA1, one2, accf[1]); accf[1] = ffma2(fB1, one2, accf[1]);
#pragma unroll
    for (int k = 0; k < 4; k++) {
        acc_e[0][k] = ffma2(fA0, eA[k], acc_e[0][k]);
        acc_e[0][k] = ffma2(fB0, eB[k], acc_e[0][k]);
        acc_d[0][k] = ffma2(fA0, dA[k], acc_d[0][k]);
        acc_d[0][k] = ffma2(fB0, dB[k], acc_d[0][k]);
        acc_e[1][k] = ffma2(fA1, eA[k], acc_e[1][k]);
        acc_e[1][k] = ffma2(fB1, eB[k], acc_e[1][k]);
        acc_d[1][k] = ffma2(fA1, dA[k], acc_d[1][k]);
        acc_d[1][k] = ffma2(fB1, dB[k], acc_d[1][k]);
    }
}
__global__ void __launch_bounds__(512, 1) k4_contract(const float* __restrict__ feat) {
    int n = blockIdx.y;
    int warp = threadIdx.x >> 5;
    int lane = threadIdx.x & 31;
    int c0 = warp * 2;
    int q0 = blockIdx.x * (32 * K4_ITER) + lane;

    const float* __restrict__ fb = feat + (size_t)n * Cc * Pp;
    const __nv_bfloat16* __restrict__ eb = g_ero + (size_t)n * NCk * Pp;
    const __nv_bfloat16* __restrict__ db = g_A   + (size_t)n * NCk * Pp;

    u64 acc_e[2][4], acc_d[2][4], accf[2];
#pragma unroll
    for (int j = 0; j < 2; j++) {
        accf[j] = 0ull;
#pragma unroll
        for (int k = 0; k < 4; k++) { acc_e[j][k] = 0ull; acc_d[j][k] = 0ull; }
    }
    const u64 one2 = pack2(1.0f, 1.0f);

    uint2 e0[4], d0[4], e1[4], d1[4];
    size_t p = (size_t)q0 * 4;
    k4_loadED(eb, db, p, e0, d0);
    for (int i = 0; i < K4_ITER; i += 2) {
        size_t pn = p + 128;
        k4_loadED(eb, db, pn, e1, d1);
        k4_body(fb, c0, p, e0, d0, acc_e, acc_d, accf, one2);
        size_t pn2 = p + 256;
        if (i + 2 < K4_ITER) k4_loadED(eb, db, pn2, e0, d0);
        k4_body(fb, c0, pn, e1, d1, acc_e, acc_d, accf, one2);
        p = pn2;
    }

#pragma unroll
    for (int j = 0; j < 2; j++) {
#pragma unroll
        for (int k = 0; k < 4; k++) {
            float l0, h0, l1, h1;
            unpack2(acc_e[j][k], l0, h0);
            unpack2(acc_d[j][k], l1, h1);
            float ae = l0 + h0, ad = l1 + h1;
#pragma unroll
            for (int o = 16; o; o >>= 1) {
                ae += __shfl_down_sync(0xffffffffu, ae, o);
                ad += __shfl_down_sync(0xffffffffu, ad, o);
            }
            if (lane == 0) {
                atomicAdd(&g_sum_fe[(n * NCk + k) * Cc + c0 + j], (double)ae);
                atomicAdd(&g_sum_fd[(n * NCk + k) * Cc + c0 + j], (double)ad);
            }
        }
        float lf, hf;
        unpack2(accf[j], lf, hf);
        float af = lf + hf;
#pragma unroll
        for (int o = 16; o; o >>= 1) af += __shfl_down_sync(0xffffffffu, af, o);
        if (lane == 0) atomicAdd(&g_sum_f[n * Cc + c0 + j], (double)af);
    }
}

// ---------------- cluster build + partial reduction ----------------
__global__ void k5_cluster() {
    __shared__ float s_back[Nn][NCk][Cc];
    __shared__ double s_se[8], s_sd[8];
    int t = threadIdx.x;
    int warp = t >> 5, lane = t & 31;
    {
        double se = 0.0;
        for (int j = lane; j < 864; j += 32) se += (double)g_parte[warp * 864 + j];
        double sd = 0.0;
        for (int j = lane; j < 216; j += 32) sd += (double)g_partd[warp * 216 + j];
#pragma unroll
        for (int o = 16; o; o >>= 1) {
            se += __shfl_down_sync(0xffffffffu, se, o);
            sd += __shfl_down_sync(0xffffffffu, sd, o);
        }
        if (lane == 0) { s_se[warp] = se; s_sd[warp] = sd; }
    }
    __syncthreads();
    int n = t >> 7;
    int k = (t >> 5) & 3;
    int c = t & 31;
    double es = s_se[n * NCk + k] + 1e-5;
    double ds = s_sd[n * NCk + k] + 1e-5;
    double bs = (double)Pp - s_sd[n * NCk + k] + 1e-5;
    double fe = g_sum_fe[(n * NCk + k) * Cc + c];
    double fd = g_sum_fd[(n * NCk + k) * Cc + c];
    double fs = g_sum_f[n * Cc + c];
    float fore = (float)(fe / es + fd / ds);
    float back = (float)((fs - fd) / bs);
    s_back[n][k][c] = back;
    g_dclu[(n * NCk + k) * Cc + c] = fore - back;
    __syncthreads();
    if (t < 64) {
        int nn = t >> 5, cc = t & 31;
        g_base[nn * Cc + cc] = ((s_back[nn][0][cc] + s_back[nn][1][cc]) +
                                (s_back[nn][2][cc] + s_back[nn][3][cc]));
    }
}

// ---------------- quad attention weights (sigmoid of logit diff) ----------------
template <bool STATS>
__device__ __forceinline__ void quad_w(const float* __restrict__ fb, size_t p,
                                       const u64 sd2[4][32],
                                       u64 wA2[4], u64 wB2[4], float wsum[4]) {
    u64 dA[4] = {0,0,0,0}, dB[4] = {0,0,0,0};
#pragma unroll
    for (int c = 0; c < 32; c++) {
        u64 fA, fB;
        ldg2x2(fb + (size_t)c * Pp + p, fA, fB);
#pragma unroll
        for (int k = 0; k < 4; k++) {
            u64 dc = sd2[k][c];
            dA[k] = ffma2(fA, dc, dA[k]);
            dB[k] = ffma2(fB, dc, dB[k]);
        }
    }
#pragma unroll
    for (int k = 0; k < 4; k++) {
        float a0, a1, a2, a3;
        unpack2(dA[k], a0, a1);
        unpack2(dB[k], a2, a3);
        float w0 = sigf(a0), w1 = sigf(a1), w2 = sigf(a2), w3 = sigf(a3);
        wA2[k] = pack2(w0, w1);
        wB2[k] = pack2(w2, w3);
        if (STATS) wsum[k] += (w0 + w1) + (w2 + w3);
    }
}

// ---------------- pass 1: BN statistics (ssq + W0) ----------------
#define K6B 128
#define K6_VOX 8
__global__ void __launch_bounds__(K6B) k6_stats(const float* __restrict__ feat,
                                                const float* __restrict__ kptr) {
    int n = blockIdx.y;
    int t = threadIdx.x;
    __shared__ u64 s_dclu2[4][32];
    __shared__ u64 s_base2[32];
    __shared__ float s_wq[4][32];
    __shared__ float s_w0[4][4];
    {
        float v = g_dclu[n * 128 + t];
        s_dclu2[t >> 5][t & 31] = pack2(v, v);
        if (t < 32) { float b = g_base[n * 32 + t]; s_base2[t] = pack2(b, b); }
    }
    float kk = kptr[0];
    __syncthreads();

    const float* __restrict__ fb = feat + (size_t)n * Cc * Pp;
    const u64 five2 = pack2(5.0f, 5.0f);
    const u64 kk2 = pack2(kk, kk);

    u64 ssq2[32];
#pragma unroll
    for (int c = 0; c < 32; c++) ssq2[c] = 0ull;
    float wsum[4] = {0.f, 0.f, 0.f, 0.f};

    int qbase = blockIdx.x * (K6B * K6_VOX) + t;
    for (int it = 0; it < K6_VOX; it++) {
        size_t p = (size_t)(qbase + it * K6B) * 4;
        u64 wA2[4], wB2[4];
        quad_w<true>(fb, p, s_dclu2, wA2, wB2, wsum);
#pragma unroll
        for (int c = 0; c < 32; c++) {
            u64 fA, fB;
            ldg2x2(fb + (size_t)c * Pp + p, fA, fB);
            u64 aA = s_base2[c], aB = s_base2[c];
#pragma unroll
            for (int k = 0; k < 4; k++) {
                u64 dc = s_dclu2[k][c];
                aA = ffma2(wA2[k], dc, aA);
                aB = ffma2(wB2[k], dc, aB);
            }
            u64 oA = ffma2(fA, five2, fmul2(kk2, aA));
            u64 oB = ffma2(fB, five2, fmul2(kk2, aB));
            ssq2[c] = ffma2(oA, oA, ssq2[c]);
            ssq2[c] = ffma2(oB, oB, ssq2[c]);
        }
    }

    int lane = t & 31, warp = t >> 5;
#pragma unroll
    for (int c = 0; c < 32; c++) {
        float lo, hi;
        unpack2(ssq2[c], lo, hi);
        float q = lo + hi;
#pragma unroll
        for (int o = 16; o; o >>= 1) q += __shfl_down_sync(0xffffffffu, q, o);
        if (lane == 0) s_wq[warp][c] = q;
    }
#pragma unroll
    for (int k = 0; k < 4; k++) {
        float s = wsum[k];
#pragma unroll
        for (int o = 16; o; o >>= 1) s += __shfl_down_sync(0xffffffffu, s, o);
        if (lane == 0) s_w0[warp][k] = s;
    }
    __syncthreads();
    if (t < 32) {
        float q = ((s_wq[0][t] + s_wq[1][t]) + (s_wq[2][t] + s_wq[3][t]));
        atomicAdd(&g_ch_sq[t], (double)q);
    }
    if (t >= 32 && t < 36) {
        int k = t - 32;
        float s = ((s_w0[0][k] + s_w0[1][k]) + (s_w0[2][k] + s_w0[3][k]));
        atomicAdd(&g_W0[n * NCk + k], (double)s);
    }
}

// ---------------- BN scale/shift (analytic mean) ----------------
__global__ void k7_bn(const float* __restrict__ bw, const float* __restrict__ bb,
                      const float* __restrict__ kptr) {
    int c = threadIdx.x;
    if (c < Cc) {
        double kkd = (double)kptr[0];
        double tot = 0.0;
#pragma unroll
        for (int n = 0; n < Nn; n++) {
            double a = (double)Pp * (double)g_base[n * Cc + c];
#pragma unroll
            for (int k = 0; k < 4; k++)
                a += (double)g_dclu[(n * NCk + k) * Cc + c] * g_W0[n * NCk + k];
            tot += 5.0 * g_sum_f[n * Cc + c] + kkd * a;
        }
        double cnt = (double)Nn * (double)Pp;
        double mean = tot / cnt;
        double var = g_ch_sq[c] / cnt - mean * mean;
        double inv = 1.0 / sqrt(var + 1e-5);
        double sc = bw[c] * inv;
        g_scale[c] = (float)sc;
        g_shift[c] = (float)(bb[c] - mean * sc);
    }
}

// ---------------- pass 2: recompute attention + normalize + write ----------------
#define K8B 256
#define K8_VOX 4
__global__ void __launch_bounds__(K8B) k8_out(const float* __restrict__ feat,
                                              const float* __restrict__ kptr,
                                              float* __restrict__ out) {
    int n = blockIdx.y;
    int t = threadIdx.x;
    __shared__ u64 s_dclu2[4][32];
    __shared__ u64 s_base2[32];
    __shared__ u64 s_sc2[32], s_sh2[32];
    if (t < 128) {
        float v = g_dclu[n * 128 + t];
        s_dclu2[t >> 5][t & 31] = pack2(v, v);
    }
    if (t >= 128 && t < 160) {
        int c = t - 128;
        float b = g_base[n * 32 + c];
        s_base2[c] = pack2(b, b);
    }
    if (t >= 160 && t < 192) {
        int c = t - 160;
        s_sc2[c] = pack2(g_scale[c], g_scale[c]);
        s_sh2[c] = pack2(g_shift[c], g_shift[c]);
    }
    float kk = kptr[0];
    __syncthreads();

    const float* __restrict__ fb = feat + (size_t)n * Cc * Pp;
    float* __restrict__ ob = out + (size_t)n * Cc * Pp;
    const u64 five2 = pack2(5.0f, 5.0f);
    const u64 kk2 = pack2(kk, kk);

    int qbase = blockIdx.x * (K8B * K8_VOX) + t;
    for (int it = 0; it < K8_VOX; it++) {
        size_t p = (size_t)(qbase + it * K8B) * 4;
        u64 wA2[4], wB2[4];
        float dummy[4];
        quad_w<false>(fb, p, s_dclu2, wA2, wB2, dummy);
#pragma unroll
        for (int c = 0; c < 32; c++) {
            u64 fA, fB;
            ldg2x2(fb + (size_t)c * Pp + p, fA, fB);
            u64 aA = s_base2[c], aB = s_base2[c];
#pragma unroll
            for (int k = 0; k < 4; k++) {
                u64 dc = s_dclu2[k][c];
                aA = ffma2(wA2[k], dc, aA);
                aB = ffma2(wB2[k], dc, aB);
            }
            u64 oA = ffma2(fA, five2, fmul2(kk2, aA));
            u64 oB = ffma2(fB, five2, fmul2(kk2, aB));
            oA = ffma2(oA, s_sc2[c], s_sh2[c]);
            oB = ffma2(oB, s_sc2[c], s_sh2[c]);
            stg2x2(ob + (size_t)c * Pp + p, oA, oB);
        }
    }
}

// ---------------- launcher ----------------
extern "C" void kernel_launch(void* const* d_in, const int* in_sizes, int n_in,
                              void* d_out, int out_size) {
    const float* feat = nullptr;
    const float* x    = nullptr;
    const float* kp   = nullptr;
    const float* bw   = nullptr;
    const float* bb   = nullptr;
    for (int i = 0; i < n_in; i++) {
        int s = in_sizes[i];
        const float* p = (const float*)d_in[i];
        if (s == NCP)        feat = p;
        else if (s == NNCP)  x = p;
        else if (s == 1)     kp = p;
        else if (s == Cc)    { if (!bw) bw = p; else bb = p; }
    }
    float* out = (float*)d_out;

    k_pool_h_erode<<<NNCP4 / 256, 256>>>((const float4*)x);
    k_pool_w<<<(U4v / 2) / 256, 256>>>();
    k_pool_d<<<(U4v / 2) / 256, 256>>>();
    k4_contract<<<dim3(Pp4 / (32 * K4_ITER), Nn), 512>>>(feat);
    k5_cluster<<<1, 256>>>();
    k6_stats<<<dim3(Pp4 / (K6B * K6_VOX), Nn), K6B>>>(feat, kp);
    k7_bn<<<1, 32>>>(bw, bb, kp);
    k8_out<<<dim3(Pp4 / (K8B * K8_VOX), Nn), K8B>>>(feat, kp, out);
}

// round 17
// speedup vs baseline: 1.1059x; 1.0587x over previous
#include <cuda_runtime.h>
#include <cuda_bf16.h>
#include <math.h>

#define Nn 2
#define Cc 32
#define NCk 4
#define Pp 884736            // 96*96*96
#define Pp4 221184           // Pp/4
#define NNCP 7077888         // Nn*NCk*Pp
#define NNCP4 1769472        // NNCP/4
#define U4v 884736           // NNCP/8 (uint4 bf16x8 units)
#define NCP  56623104        // Nn*Cc*Pp

#define PINF  __int_as_float(0x7f800000)
#define NINF  __int_as_float(0xff800000)
#define BNEG2 0xFF80FF80u    // bf16x2 {-inf,-inf}

typedef unsigned long long u64;
typedef unsigned int u32;

// ---------------- f32x2 helpers ----------------
__device__ __forceinline__ u64 pack2(float lo, float hi) {
    u64 r; asm("mov.b64 %0,{%1,%2};" : "=l"(r) : "f"(lo), "f"(hi)); return r;
}
__device__ __forceinline__ void unpack2(u64 v, float& lo, float& hi) {
    asm("mov.b64 {%0,%1},%2;" : "=f"(lo), "=f"(hi) : "l"(v));
}
__device__ __forceinline__ u64 ffma2(u64 a, u64 b, u64 c) {
    u64 d; asm("fma.rn.f32x2 %0,%1,%2,%3;" : "=l"(d) : "l"(a), "l"(b), "l"(c)); return d;
}
__device__ __forceinline__ u64 fmul2(u64 a, u64 b) {
    u64 d; asm("mul.rn.f32x2 %0,%1,%2;" : "=l"(d) : "l"(a), "l"(b)); return d;
}
__device__ __forceinline__ void ldg2x2(const float* p, u64& a, u64& b) {
    asm volatile("ld.global.v2.u64 {%0,%1},[%2];" : "=l"(a), "=l"(b) : "l"(p));
}
__device__ __forceinline__ void ldg2x2_nc(const float* p, u64& a, u64& b) {
    asm volatile("ld.global.nc.v2.u64 {%0,%1},[%2];" : "=l"(a), "=l"(b) : "l"(p));
}
__device__ __forceinline__ void stg2x2_cs(float* p, u64 a, u64 b) {
    asm volatile("st.global.cs.v2.u64 [%0],{%1,%2};" :: "l"(p), "l"(a), "l"(b) : "memory");
}
__device__ __forceinline__ uint2 ldg_u2_nc(const void* p) {
    uint2 v;
    asm volatile("ld.global.nc.v2.u32 {%0,%1},[%2];" : "=r"(v.x), "=r"(v.y) : "l"(p));
    return v;
}
__device__ __forceinline__ u32 packbf2(float lo, float hi) {
    u32 r; asm("cvt.rn.bf16x2.f32 %0,%1,%2;" : "=r"(r) : "f"(hi), "f"(lo)); return r;
}
__device__ __forceinline__ void bf4_to_f32x2(uint2 v, u64& A, u64& B) {
    A = pack2(__uint_as_float(v.x << 16), __uint_as_float(v.x & 0xFFFF0000u));
    B = pack2(__uint_as_float(v.y << 16), __uint_as_float(v.y & 0xFFFF0000u));
}
__device__ __forceinline__ u32 bmax2(u32 a, u32 b) {
    __nv_bfloat162 r = __hmax2(*reinterpret_cast<__nv_bfloat162*>(&a),
                               *reinterpret_cast<__nv_bfloat162*>(&b));
    return *reinterpret_cast<u32*>(&r);
}
__device__ __forceinline__ uint4 bmax8(uint4 a, uint4 b) {
    return make_uint4(bmax2(a.x,b.x), bmax2(a.y,b.y), bmax2(a.z,b.z), bmax2(a.w,b.w));
}
__device__ __forceinline__ float sigf(float v) { return 1.0f / (1.0f + __expf(-v)); }

// ---------------- scratch ----------------
__device__ __align__(16) __nv_bfloat16 g_A[NNCP];
__device__ __align__(16) __nv_bfloat16 g_B[NNCP];
__device__ __align__(16) __nv_bfloat16 g_ero[NNCP];

__device__ float  g_parte[6912];
__device__ float  g_partd[1728];
__device__ double g_sum_fe[Nn * NCk * Cc];
__device__ double g_sum_fd[Nn * NCk * Cc];
__device__ double g_sum_f [Nn * Cc];
__device__ double g_ch_sq [Cc];
__device__ double g_W0    [Nn * NCk];
__device__ float  g_dclu[Nn * NCk * Cc];
__device__ float  g_base[Nn * Cc];
__device__ float  g_scale[Cc];
__device__ float  g_shift[Cc];

__device__ __forceinline__ float4 vmin4(float4 a, float4 b) {
    return make_float4(fminf(a.x,b.x), fminf(a.y,b.y), fminf(a.z,b.z), fminf(a.w,b.w));
}

// ---------------- fused: h-max pool + full erode + partial ero sums + zeroing ----------------
__global__ void __launch_bounds__(256) k_pool_h_erode(const float4* __restrict__ x4) {
    int i = blockIdx.x * blockDim.x + threadIdx.x;
    int t = threadIdx.x;
    __shared__ float s_red[8];
    if (blockIdx.x == 0) {
        if (t < 256) { g_sum_fe[t] = 0.0; g_sum_fd[t] = 0.0; }
        if (t < 64)  g_sum_f[t] = 0.0;
        if (t < 32)  g_ch_sq[t] = 0.0;
        if (t < 8)   g_W0[t] = 0.0;
    }
    int h4 = i % 24;
    int w = (i / 24) % 96;
    int d = (i / 2304) % 96;
    bool hasP = (h4 >= 1), hasN = (h4 <= 22);
    float4 cur = x4[i];
    float4 pv = make_float4(0,0,0,0), nv = make_float4(0,0,0,0);
    if (hasP) pv = x4[i-1];
    if (hasN) nv = x4[i+1];

    {
        float s[12];
        s[0] = hasP ? pv.x : NINF; s[1] = hasP ? pv.y : NINF;
        s[2] = hasP ? pv.z : NINF; s[3] = hasP ? pv.w : NINF;
        s[4]=cur.x; s[5]=cur.y; s[6]=cur.z; s[7]=cur.w;
        s[8] = hasN ? nv.x : NINF; s[9] = hasN ? nv.y : NINF;
        s[10]= hasN ? nv.z : NINF; s[11]= hasN ? nv.w : NINF;
        float o0 = fmaxf(fmaxf(fmaxf(s[2],s[3]), fmaxf(s[4],s[5])), s[6]);
        float o1 = fmaxf(fmaxf(fmaxf(s[3],s[4]), fmaxf(s[5],s[6])), s[7]);
        float o2 = fmaxf(fmaxf(fmaxf(s[4],s[5]), fmaxf(s[6],s[7])), s[8]);
        float o3 = fmaxf(fmaxf(fmaxf(s[5],s[6]), fmaxf(s[7],s[8])), s[9]);
        reinterpret_cast<uint2*>(g_A)[i] = make_uint2(packbf2(o0,o1), packbf2(o2,o3));
    }
    float esum;
    {
        float s[12];
        s[0] = hasP ? pv.x : PINF; s[1] = hasP ? pv.y : PINF;
        s[2] = hasP ? pv.z : PINF; s[3] = hasP ? pv.w : PINF;
        s[4]=cur.x; s[5]=cur.y; s[6]=cur.z; s[7]=cur.w;
        s[8] = hasN ? nv.x : PINF; s[9] = hasN ? nv.y : PINF;
        s[10]= hasN ? nv.z : PINF; s[11]= hasN ? nv.w : PINF;
        float4 m;
        m.x = fminf(fminf(fminf(s[2],s[3]), fminf(s[4],s[5])), s[6]);
        m.y = fminf(fminf(fminf(s[3],s[4]), fminf(s[5],s[6])), s[7]);
        m.z = fminf(fminf(fminf(s[4],s[5]), fminf(s[6],s[7])), s[8]);
        m.w = fminf(fminf(fminf(s[5],s[6]), fminf(s[7],s[8])), s[9]);
        if (w >= 1)  m = vmin4(m, x4[i - 24]);
        if (w >= 2)  m = vmin4(m, x4[i - 48]);
        if (w <= 94) m = vmin4(m, x4[i + 24]);
        if (w <= 93) m = vmin4(m, x4[i + 48]);
        if (d >= 1)  m = vmin4(m, x4[i - 2304]);
        if (d >= 2)  m = vmin4(m, x4[i - 4608]);
        if (d <= 94) m = vmin4(m, x4[i + 2304]);
        if (d <= 93) m = vmin4(m, x4[i + 4608]);
        m.x = sigf(m.x); m.y = sigf(m.y); m.z = sigf(m.z); m.w = sigf(m.w);
        reinterpret_cast<uint2*>(g_ero)[i] = make_uint2(packbf2(m.x,m.y), packbf2(m.z,m.w));
        esum = (m.x + m.y) + (m.z + m.w);
    }
#pragma unroll
    for (int o = 16; o; o >>= 1) esum += __shfl_down_sync(0xffffffffu, esum, o);
    if ((t & 31) == 0) s_red[t >> 5] = esum;
    __syncthreads();
    if (t == 0) {
        float bsum = 0.f;
#pragma unroll
        for (int wv = 0; wv < 8; wv++) bsum += s_red[wv];
        g_parte[blockIdx.x] = bsum;
    }
}

// ---------------- pool along W (bf16 uint4 = 8 voxels), paired, g_A -> g_B ----------------
__global__ void __launch_bounds__(256) k_pool_w() {
    int j = blockIdx.x * blockDim.x + threadIdx.x;
    const uint4* __restrict__ in = reinterpret_cast<const uint4*>(g_A);
    uint4* __restrict__ outp = reinterpret_cast<uint4*>(g_B);
    int h  = j % 12;
    int wp = (j / 12) % 48;
    int rest = j / 576;
    int i0 = rest * 1152 + wp * 24 + h;
    const uint4 NEG = make_uint4(BNEG2, BNEG2, BNEG2, BNEG2);
    uint4 c0 = in[i0];
    uint4 p1 = in[i0 + 12];
    uint4 m1 = (wp >= 1) ? in[i0 - 12] : NEG;
    uint4 m2 = (wp >= 1) ? in[i0 - 24] : NEG;
    uint4 p2 = (wp <= 46) ? in[i0 + 24] : NEG;
    uint4 p3 = (wp <= 46) ? in[i0 + 36] : NEG;
    outp[i0]      = bmax8(bmax8(bmax8(m2, m1), bmax8(c0, p1)), p2);
    outp[i0 + 12] = bmax8(bmax8(bmax8(m1, c0), bmax8(p1, p2)), p3);
}

// ---------------- pool along D (bf16), paired + sigmoid + partial dil sums ----------------
__device__ __forceinline__ u32 sig_bf2(u32 bits, float& acc) {
    float f0 = sigf(__uint_as_float(bits << 16));
    float f1 = sigf(__uint_as_float(bits & 0xFFFF0000u));
    acc += f0 + f1;
    return packbf2(f0, f1);
}
__global__ void __launch_bounds__(256) k_pool_d() {
    int j = blockIdx.x * blockDim.x + threadIdx.x;
    int t = threadIdx.x;
    __shared__ float s_red[8];
    const uint4* __restrict__ in = reinterpret_cast<const uint4*>(g_B);
    uint4* __restrict__ outp = reinterpret_cast<uint4*>(g_A);
    int hh = j % 1152;
    int dp = (j / 1152) % 48;
    int nk = j / 55296;
    int i0 = nk * 110592 + dp * 2304 + hh;
    const uint4 NEG = make_uint4(BNEG2, BNEG2, BNEG2, BNEG2);
    uint4 c0 = in[i0];
    uint4 p1 = in[i0 + 1152];
    uint4 m1 = (dp >= 1) ? in[i0 - 1152] : NEG;
    uint4 m2 = (dp >= 1) ? in[i0 - 2304] : NEG;
    uint4 p2 = (dp <= 46) ? in[i0 + 2304] : NEG;
    uint4 p3 = (dp <= 46) ? in[i0 + 3456] : NEG;
    uint4 o0 = bmax8(bmax8(bmax8(m2, m1), bmax8(c0, p1)), p2);
    uint4 o1 = bmax8(bmax8(bmax8(m1, c0), bmax8(p1, p2)), p3);
    float dsum = 0.f;
    o0.x = sig_bf2(o0.x, dsum); o0.y = sig_bf2(o0.y, dsum);
    o0.z = sig_bf2(o0.z, dsum); o0.w = sig_bf2(o0.w, dsum);
    o1.x = sig_bf2(o1.x, dsum); o1.y = sig_bf2(o1.y, dsum);
    o1.z = sig_bf2(o1.z, dsum); o1.w = sig_bf2(o1.w, dsum);
    outp[i0] = o0;
    outp[i0 + 1152] = o1;
#pragma unroll
    for (int o = 16; o; o >>= 1) dsum += __shfl_down_sync(0xffffffffu, dsum, o);
    if ((t & 31) == 0) s_red[t >> 5] = dsum;
    __syncthreads();
    if (t == 0) {
        float bsum = 0.f;
#pragma unroll
        for (int wv = 0; wv < 8; wv++) bsum += s_red[wv];
        g_partd[blockIdx.x] = bsum;
    }
}

// ---------------- contraction (bf16 masks, double-buffered, nc mask loads) ----------------
#define K4_ITER 32
__device__ __forceinline__ void k4_loadED(const __nv_bfloat16* __restrict__ eb,
                                          const __nv_bfloat16* __restrict__ db,
                                          size_t p, uint2 ev[4], uint2 dv[4]) {
#pragma unroll
    for (int k = 0; k < 4; k++) {
        ev[k] = ldg_u2_nc(eb + (size_t)k * Pp + p);
        dv[k] = ldg_u2_nc(db + (size_t)k * Pp + p);
    }
}
__device__ __forceinline__ void k4_body(const float* __restrict__ fb, int c0, size_t p,
                                        const uint2 ev[4], const uint2 dv[4],
                                        u64 acc_e[2][4], u64 acc_d[2][4], u64 accf[2], u64 one2) {
    u64 fA0, fB0, fA1, fB1;
    ldg2x2(fb + (size_t)c0 * Pp + p, fA0, fB0);
    ldg2x2(fb + (size_t)(c0 + 1) * Pp + p, fA1, fB1);
    u64 eA[4], eB[4], dA[4], dB[4];
#pragma unroll
    for (int k = 0; k < 4; k++) {
        bf4_to_f32x2(ev[k], eA[k], eB[k]);
        bf4_to_f32x2(dv[k], dA[k], dB[k]);
    }
    accf[0] = ffma2(fA0, one2, accf[0]); accf[0] = ffma2(fB0, one2, accf[0]);
    accf[1] = ffma2(fA1, one2, accf[1]); accf[1] = ffma2(fB1, one2, accf[1]);
#pragma unroll
    for (int k = 0; k < 4; k++) {
        acc_e[0][k] = ffma2(fA0, eA[k], acc_e[0][k]);
        acc_e[0][k] = ffma2(fB0, eB[k], acc_e[0][k]);
        acc_d[0][k] = ffma2(fA0, dA[k], acc_d[0][k]);
        acc_d[0][k] = ffma2(fB0, dB[k], acc_d[0][k]);
        acc_e[1][k] = ffma2(fA1, eA[k], acc_e[1][k]);
        acc_e[1][k] = ffma2(fB1, eB[k], acc_e[1][k]);
        acc_d[1][k] = ffma2(fA1, dA[k], acc_d[1][k]);
        acc_d[1][k] = ffma2(fB1, dB[k], acc_d[1][k]);
    }
}
__global__ void __launch_bounds__(512, 1) k4_contract(const float* __restrict__ feat) {
    int n = blockIdx.y;
    int warp = threadIdx.x >> 5;
    int lane = threadIdx.x & 31;
    int c0 = warp * 2;
    int q0 = blockIdx.x * (32 * K4_ITER) + lane;

    const float* __restrict__ fb = feat + (size_t)n * Cc * Pp;
    const __nv_bfloat16* __restrict__ eb = g_ero + (size_t)n * NCk * Pp;
    const __nv_bfloat16* __restrict__ db = g_A   + (size_t)n * NCk * Pp;

    u64 acc_e[2][4], acc_d[2][4], accf[2];
#pragma unroll
    for (int j = 0; j < 2; j++) {
        accf[j] = 0ull;
#pragma unroll
        for (int k = 0; k < 4; k++) { acc_e[j][k] = 0ull; acc_d[j][k] = 0ull; }
    }
    const u64 one2 = pack2(1.0f, 1.0f);

    uint2 e0[4], d0[4], e1[4], d1[4];
    size_t p = (size_t)q0 * 4;
    k4_loadED(eb, db, p, e0, d0);
    for (int i = 0; i < K4_ITER; i += 2) {
        size_t pn = p + 128;
        k4_loadED(eb, db, pn, e1, d1);
        k4_body(fb, c0, p, e0, d0, acc_e, acc_d, accf, one2);
        size_t pn2 = p + 256;
        if (i + 2 < K4_ITER) k4_loadED(eb, db, pn2, e0, d0);
        k4_body(fb, c0, pn, e1, d1, acc_e, acc_d, accf, one2);
        p = pn2;
    }

#pragma unroll
    for (int j = 0; j < 2; j++) {
#pragma unroll
        for (int k = 0; k < 4; k++) {
            float l0, h0, l1, h1;
            unpack2(acc_e[j][k], l0, h0);
            unpack2(acc_d[j][k], l1, h1);
            float ae = l0 + h0, ad = l1 + h1;
#pragma unroll
            for (int o = 16; o; o >>= 1) {
                ae += __shfl_down_sync(0xffffffffu, ae, o);
                ad += __shfl_down_sync(0xffffffffu, ad, o);
            }
            if (lane == 0) {
                atomicAdd(&g_sum_fe[(n * NCk + k) * Cc + c0 + j], (double)ae);
                atomicAdd(&g_sum_fd[(n * NCk + k) * Cc + c0 + j], (double)ad);
            }
        }
        float lf, hf;
        unpack2(accf[j], lf, hf);
        float af = lf + hf;
#pragma unroll
        for (int o = 16; o; o >>= 1) af += __shfl_down_sync(0xffffffffu, af, o);
        if (lane == 0) atomicAdd(&g_sum_f[n * Cc + c0 + j], (double)af);
    }
}

// ---------------- cluster build + partial reduction ----------------
__global__ void k5_cluster() {
    __shared__ float s_back[Nn][NCk][Cc];
    __shared__ double s_se[8], s_sd[8];
    int t = threadIdx.x;
    int warp = t >> 5, lane = t & 31;
    {
        double se = 0.0;
        for (int j = lane; j < 864; j += 32) se += (double)g_parte[warp * 864 + j];
        double sd = 0.0;
        for (int j = lane; j < 216; j += 32) sd += (double)g_partd[warp * 216 + j];
#pragma unroll
        for (int o = 16; o; o >>= 1) {
            se += __shfl_down_sync(0xffffffffu, se, o);
            sd += __shfl_down_sync(0xffffffffu, sd, o);
        }
        if (lane == 0) { s_se[warp] = se; s_sd[warp] = sd; }
    }
    __syncthreads();
    int n = t >> 7;
    int k = (t >> 5) & 3;
    int c = t & 31;
    double es = s_se[n * NCk + k] + 1e-5;
    double ds = s_sd[n * NCk + k] + 1e-5;
    double bs = (double)Pp - s_sd[n * NCk + k] + 1e-5;
    double fe = g_sum_fe[(n * NCk + k) * Cc + c];
    double fd = g_sum_fd[(n * NCk + k) * Cc + c];
    double fs = g_sum_f[n * Cc + c];
    float fore = (float)(fe / es + fd / ds);
    float back = (float)((fs - fd) / bs);
    s_back[n][k][c] = back;
    g_dclu[(n * NCk + k) * Cc + c] = fore - back;
    __syncthreads();
    if (t < 64) {
        int nn = t >> 5, cc = t & 31;
        g_base[nn * Cc + cc] = ((s_back[nn][0][cc] + s_back[nn][1][cc]) +
                                (s_back[nn][2][cc] + s_back[nn][3][cc]));
    }
}

// ---------------- quad attention weights (sigmoid of logit diff) ----------------
template <bool STATS>
__device__ __forceinline__ void quad_w(const float* __restrict__ fb, size_t p,
                                       const u64 sd2[4][32],
                                       u64 wA2[4], u64 wB2[4], float wsum[4]) {
    u64 dA[4] = {0,0,0,0}, dB[4] = {0,0,0,0};
#pragma unroll
    for (int c = 0; c < 32; c++) {
        u64 fA, fB;
        ldg2x2(fb + (size_t)c * Pp + p, fA, fB);
#pragma unroll
        for (int k = 0; k < 4; k++) {
            u64 dc = sd2[k][c];
            dA[k] = ffma2(fA, dc, dA[k]);
            dB[k] = ffma2(fB, dc, dB[k]);
        }
    }
#pragma unroll
    for (int k = 0; k < 4; k++) {
        float a0, a1, a2, a3;
        unpack2(dA[k], a0, a1);
        unpack2(dB[k], a2, a3);
        float w0 = sigf(a0), w1 = sigf(a1), w2 = sigf(a2), w3 = sigf(a3);
        wA2[k] = pack2(w0, w1);
        wB2[k] = pack2(w2, w3);
        if (STATS) wsum[k] += (w0 + w1) + (w2 + w3);
    }
}

// ---------------- pass 1: BN statistics (ssq + W0) ----------------
#define K6B 128
#define K6_VOX 8
__global__ void __launch_bounds__(K6B) k6_stats(const float* __restrict__ feat,
                                                const float* __restrict__ kptr) {
    int n = blockIdx.y;
    int t = threadIdx.x;
    __shared__ u64 s_dclu2[4][32];
    __shared__ u64 s_base2[32];
    __shared__ float s_wq[4][32];
    __shared__ float s_w0[4][4];
    {
        float v = g_dclu[n * 128 + t];
        s_dclu2[t >> 5][t & 31] = pack2(v, v);
        if (t < 32) { float b = g_base[n * 32 + t]; s_base2[t] = pack2(b, b); }
    }
    float kk = kptr[0];
    __syncthreads();

    const float* __restrict__ fb = feat + (size_t)n * Cc * Pp;
    const u64 five2 = pack2(5.0f, 5.0f);
    const u64 kk2 = pack2(kk, kk);

    u64 ssq2[32];
#pragma unroll
    for (int c = 0; c < 32; c++) ssq2[c] = 0ull;
    float wsum[4] = {0.f, 0.f, 0.f, 0.f};

    int qbase = blockIdx.x * (K6B * K6_VOX) + t;
    for (int it = 0; it < K6_VOX; it++) {
        size_t p = (size_t)(qbase + it * K6B) * 4;
        u64 wA2[4], wB2[4];
        quad_w<true>(fb, p, s_dclu2, wA2, wB2, wsum);
#pragma unroll
        for (int c = 0; c < 32; c++) {
            u64 fA, fB;
            ldg2x2_nc(fb + (size_t)c * Pp + p, fA, fB);
            u64 aA = s_base2[c], aB = s_base2[c];
#pragma unroll
            for (int k = 0; k < 4; k++) {
                u64 dc = s_dclu2[k][c];
                aA = ffma2(wA2[k], dc, aA);
                aB = ffma2(wB2[k], dc, aB);
            }
            u64 oA = ffma2(fA, five2, fmul2(kk2, aA));
            u64 oB = ffma2(fB, five2, fmul2(kk2, aB));
            ssq2[c] = ffma2(oA, oA, ssq2[c]);
            ssq2[c] = ffma2(oB, oB, ssq2[c]);
        }
    }

    int lane = t & 31, warp = t >> 5;
#pragma unroll
    for (int c = 0; c < 32; c++) {
        float lo, hi;
        unpack2(ssq2[c], lo, hi);
        float q = lo + hi;
#pragma unroll
        for (int o = 16; o; o >>= 1) q += __shfl_down_sync(0xffffffffu, q, o);
        if (lane == 0) s_wq[warp][c] = q;
    }
#pragma unroll
    for (int k = 0; k < 4; k++) {
        float s = wsum[k];
#pragma unroll
        for (int o = 16; o; o >>= 1) s += __shfl_down_sync(0xffffffffu, s, o);
        if (lane == 0) s_w0[warp][k] = s;
    }
    __syncthreads();
    if (t < 32) {
        float q = ((s_wq[0][t] + s_wq[1][t]) + (s_wq[2][t] + s_wq[3][t]));
        atomicAdd(&g_ch_sq[t], (double)q);
    }
    if (t >= 32 && t < 36) {
        int k = t - 32;
        float s = ((s_w0[0][k] + s_w0[1][k]) + (s_w0[2][k] + s_w0[3][k]));
        atomicAdd(&g_W0[n * NCk + k], (double)s);
    }
}

// ---------------- BN scale/shift (analytic mean) ----------------
__global__ void k7_bn(const float* __restrict__ bw, const float* __restrict__ bb,
                      const float* __restrict__ kptr) {
    int c = threadIdx.x;
    if (c < Cc) {
        double kkd = (double)kptr[0];
        double tot = 0.0;
#pragma unroll
        for (int n = 0; n < Nn; n++) {
            double a = (double)Pp * (double)g_base[n * Cc + c];
#pragma unroll
            for (int k = 0; k < 4; k++)
                a += (double)g_dclu[(n * NCk + k) * Cc + c] * g_W0[n * NCk + k];
            tot += 5.0 * g_sum_f[n * Cc + c] + kkd * a;
        }
        double cnt = (double)Nn * (double)Pp;
        double mean = tot / cnt;
        double var = g_ch_sq[c] / cnt - mean * mean;
        double inv = 1.0 / sqrt(var + 1e-5);
        double sc = bw[c] * inv;
        g_scale[c] = (float)sc;
        g_shift[c] = (float)(bb[c] - mean * sc);
    }
}

// ---------------- pass 2: recompute attention + normalize + write (streaming stores) ----------------
#define K8B 256
#define K8_VOX 4
__global__ void __launch_bounds__(K8B) k8_out(const float* __restrict__ feat,
                                              const float* __restrict__ kptr,
                                              float* __restrict__ out) {
    int n = blockIdx.y;
    int t = threadIdx.x;
    __shared__ u64 s_dclu2[4][32];
    __shared__ u64 s_base2[32];
    __shared__ u64 s_sc2[32], s_sh2[32];
    if (t < 128) {
        float v = g_dclu[n * 128 + t];
        s_dclu2[t >> 5][t & 31] = pack2(v, v);
    }
    if (t >= 128 && t < 160) {
        int c = t - 128;
        float b = g_base[n * 32 + c];
        s_base2[c] = pack2(b, b);
    }
    if (t >= 160 && t < 192) {
        int c = t - 160;
        s_sc2[c] = pack2(g_scale[c], g_scale[c]);
        s_sh2[c] = pack2(g_shift[c], g_shift[c]);
    }
    float kk = kptr[0];
    __syncthreads();

    const float* __restrict__ fb = feat + (size_t)n * Cc * Pp;
    float* __restrict__ ob = out + (size_t)n * Cc * Pp;
    const u64 five2 = pack2(5.0f, 5.0f);
    const u64 kk2 = pack2(kk, kk);

    int qbase = blockIdx.x * (K8B * K8_VOX) + t;
    for (int it = 0; it < K8_VOX; it++) {
        size_t p = (size_t)(qbase + it * K8B) * 4;
        u64 wA2[4], wB2[4];
        float dummy[4];
        quad_w<false>(fb, p, s_dclu2, wA2, wB2, dummy);
#pragma unroll
        for (int c = 0; c < 32; c++) {
            u64 fA, fB;
            ldg2x2_nc(fb + (size_t)c * Pp + p, fA, fB);
            u64 aA = s_base2[c], aB = s_base2[c];
#pragma unroll
            for (int k = 0; k < 4; k++) {
                u64 dc = s_dclu2[k][c];
                aA = ffma2(wA2[k], dc, aA);
                aB = ffma2(wB2[k], dc, aB);
            }
            u64 oA = ffma2(fA, five2, fmul2(kk2, aA));
            u64 oB = ffma2(fB, five2, fmul2(kk2, aB));
            oA = ffma2(oA, s_sc2[c], s_sh2[c]);
            oB = ffma2(oB, s_sc2[c], s_sh2[c]);
            stg2x2_cs(ob + (size_t)c * Pp + p, oA, oB);
        }
    }
}

// ---------------- launcher ----------------
extern "C" void kernel_launch(void* const* d_in, const int* in_sizes, int n_in,
                              void* d_out, int out_size) {
    const float* feat = nullptr;
    const float* x    = nullptr;
    const float* kp   = nullptr;
    const float* bw   = nullptr;
    const float* bb   = nullptr;
    for (int i = 0; i < n_in; i++) {
        int s = in_sizes[i];
        const float* p = (const float*)d_in[i];
        if (s == NCP)        feat = p;
        else if (s == NNCP)  x = p;
        else if (s == 1)     kp = p;
        else if (s == Cc)    { if (!bw) bw = p; else bb = p; }
    }
    float* out = (float*)d_out;

    k_pool_h_erode<<<NNCP4 / 256, 256>>>((const float4*)x);
    k_pool_w<<<(U4v / 2) / 256, 256>>>();
    k_pool_d<<<(U4v / 2) / 256, 256>>>();
    k4_contract<<<dim3(Pp4 / (32 * K4_ITER), Nn), 512>>>(feat);
    k5_cluster<<<1, 256>>>();
    k6_stats<<<dim3(Pp4 / (K6B * K6_VOX), Nn), K6B>>>(feat, kp);
    k7_bn<<<1, 32>>>(bw, bb, kp);
    k8_out<<<dim3(Pp4 / (K8B * K8_VOX), Nn), K8B>>>(feat, kp, out);
}